// round 9
// baseline (speedup 1.0000x reference)
#include <cuda_runtime.h>
#include <cstdint>

#define B_DIM  1024
#define H_DIM  2048
#define KTOT   6144
#define NTOT   8192
#define NCH    48
#define T_CH   35          // tensor chunks 0..34 (0-31 @INV -> acc1, 32-34 @INV2 -> acc1b)
#define D_CH   13          // dp4a chunks 35..47 (@INV2 -> acc2)
#define CHUNK_BYTES 20480  // A 16KB + B 4KB
#define T_BASE 0
#define D_BASE (4 * CHUNK_BYTES)            // 81920
#define SMEM_BYTES (8 * CHUNK_BYTES)        // 163840

// Exchange buffer lives INSIDE the dp4a group's pipeline region (dead by the
// time it is written). 128 slots x 36 ints = 18432 B.
#define EXCH_OFF D_BASE
#define CX_OFF   0                           // tensor region, used after join
#define H_OFF    (CX_OFF + 4608)
#define C_OFF    (H_OFF + 4608)

// h scale: S = 256*127/5; v = round(hx*S) in [-32511,32511]; v = hi*256 + lo
#define SCALE_H 6502.4f
#define VCLAMP  32511.0f

__device__ __align__(256) int8_t g_A[(size_t)B_DIM * KTOT];
__device__ __align__(256) int8_t g_B[(size_t)NTOT * KTOT];
__device__ float g_bias[NTOT];

// ------------------------------- helpers ----------------------------------

__device__ __forceinline__ uint32_t smem_u32(const void* p) {
    uint32_t a;
    asm("{ .reg .u64 t; cvta.to.shared.u64 t, %1; cvt.u32.u64 %0, t; }"
        : "=r"(a) : "l"(p));
    return a;
}

__device__ __forceinline__ float fq8(float v) {
    float q = rintf(v * 127.0f);
    q = fminf(127.0f, fmaxf(-127.0f, q));
    return q * (1.0f / 127.0f);
}

__device__ __forceinline__ float sigm_(float x) {
    return 1.0f / (1.0f + expf(-x));
}

__device__ __forceinline__ float tanh_(float x) {
    float e = expf(-2.0f * fabsf(x));
    return copysignf((1.0f - e) / (1.0f + e), x);
}

__device__ __forceinline__ signed char q127(float w) {
    float q = rintf(w * 127.0f);
    q = fminf(127.0f, fmaxf(-127.0f, q));
    return (signed char)(int)q;
}

// ------------------------------ prep kernels ------------------------------

__global__ void prep_A(const float* __restrict__ x, const float* __restrict__ hx) {
    const int b = blockIdx.y;
    const int c4 = blockIdx.x * 256 + threadIdx.x;      // 0..511
    const int k = c4 << 2;
    const float4 xv = *reinterpret_cast<const float4*>(x + (size_t)b * 2048 + k);
    const float4 hv = *reinterpret_cast<const float4*>(hx + (size_t)b * 2048 + k);
    const float* xf = reinterpret_cast<const float*>(&xv);
    const float* hf = reinterpret_cast<const float*>(&hv);
    char4 xq, hiq, loq;
    signed char* xp = reinterpret_cast<signed char*>(&xq);
    signed char* hp = reinterpret_cast<signed char*>(&hiq);
    signed char* lp = reinterpret_cast<signed char*>(&loq);
#pragma unroll
    for (int j = 0; j < 4; ++j) {
        xp[j] = q127(xf[j]);
        float vf = rintf(hf[j] * SCALE_H);
        vf = fminf(VCLAMP, fmaxf(-VCLAMP, vf));
        int v = (int)vf;
        int hi = (v + 128) >> 8;            // hi in [-127,127]
        int lo = v - (hi << 8);             // lo in [-128,127]
        hp[j] = (signed char)hi;
        lp[j] = (signed char)lo;
    }
    size_t base = (size_t)b * KTOT + k;
    *reinterpret_cast<char4*>(g_A + base)        = xq;
    *reinterpret_cast<char4*>(g_A + base + 2048) = hiq;
    *reinterpret_cast<char4*>(g_A + base + 4096) = loq;
}

// B row r=4u+g from orig row g*2048+u: [0,2048) wxI ; [2048,4096) whI*5 ; [4096,6144) whI
__global__ void prep_W(const float* __restrict__ wx, const float* __restrict__ wh) {
    const int r = blockIdx.y;
    const int c4 = blockIdx.x * 256 + threadIdx.x;      // 0..1535
    const int u = r >> 2, g = r & 3;
    const size_t orig = (size_t)(g * H_DIM + u) * 2048;
    char4 outv;
    signed char* op = reinterpret_cast<signed char*>(&outv);
    if (c4 < 512) {
        const float4 wv = *reinterpret_cast<const float4*>(wx + orig + (c4 << 2));
        const float* wf = reinterpret_cast<const float*>(&wv);
#pragma unroll
        for (int j = 0; j < 4; ++j) op[j] = q127(wf[j]);
    } else if (c4 < 1024) {
        const float4 wv = *reinterpret_cast<const float4*>(wh + orig + ((c4 - 512) << 2));
        const float* wf = reinterpret_cast<const float*>(&wv);
#pragma unroll
        for (int j = 0; j < 4; ++j) op[j] = (signed char)(5 * (int)q127(wf[j]));
    } else {
        const float4 wv = *reinterpret_cast<const float4*>(wh + orig + ((c4 - 1024) << 2));
        const float* wf = reinterpret_cast<const float*>(&wv);
#pragma unroll
        for (int j = 0; j < 4; ++j) op[j] = q127(wf[j]);
    }
    *reinterpret_cast<char4*>(g_B + (size_t)r * KTOT + (c4 << 2)) = outv;
}

__global__ void prep_bias(const float* __restrict__ bx, const float* __restrict__ bh) {
    int r = blockIdx.x * 256 + threadIdx.x;
    if (r >= NTOT) return;
    int u = r >> 2, g = r & 3;
    int orig = g * H_DIM + u;
    g_bias[r] = bx[orig] + bh[orig];
}

// ------------------------------- GEMM kernel ------------------------------
// CTA: 128(M) x 32(N), 256 threads, 1 CTA/SM.
// Warps 0-3: tensor group (mma.s8, 35 chunks). Warps 4-7: dp4a group (13).

__device__ __forceinline__ void prefetch_chunk(uint32_t base, int stage, int chunk,
                                               int m0, int n0, int gt) {
    const int koff = chunk << 7;
    const uint32_t sbase = base + (uint32_t)stage * CHUNK_BYTES;
#pragma unroll
    for (int p = 0; p < 10; ++p) {
        const int idx = p * 128 + gt;       // 0..1279 ; <1024 A, else B
        const bool isA = idx < 1024;
        const int v = isA ? idx : idx - 1024;
        const int row = v >> 3;
        const int q = v & 7;
        const uint32_t dst = sbase + (isA ? 0u : 16384u)
                           + (uint32_t)(row << 7)
                           + (uint32_t)((q ^ (row & 7)) << 4);
        const int8_t* src = isA
            ? g_A + (size_t)(m0 + row) * KTOT + koff + (q << 4)
            : g_B + (size_t)(n0 + row) * KTOT + koff + (q << 4);
        asm volatile("cp.async.cg.shared.global [%0], [%1], 16;"
                     :: "r"(dst), "l"(src));
    }
}

#define COMPUTE_CHUNK(ACC, SA)                                                 \
  {                                                                            \
    const uint32_t sA = (SA);                                                  \
    const uint32_t sB = sA + 16384u;                                           \
    _Pragma("unroll")                                                          \
    for (int ks = 0; ks < 4; ++ks) {                                           \
      uint32_t a[4][4], b[4];                                                  \
      _Pragma("unroll")                                                        \
      for (int mf = 0; mf < 4; ++mf) {                                         \
        const int row = wm * 64 + mf * 16 + rsel;                              \
        const uint32_t ad = sA + (uint32_t)(row << 7)                          \
                          + (uint32_t)((((ks * 2 + khalf)) ^ (row & 7)) << 4); \
        asm volatile(                                                          \
          "ldmatrix.sync.aligned.m8n8.x4.shared.b16 {%0,%1,%2,%3}, [%4];"      \
          : "=r"(a[mf][0]), "=r"(a[mf][1]), "=r"(a[mf][2]), "=r"(a[mf][3])     \
          : "r"(ad));                                                          \
      }                                                                        \
      {                                                                        \
        const int row = wn * 16 + rsel;                                        \
        const uint32_t bd = sB + (uint32_t)(row << 7)                          \
                          + (uint32_t)((((ks * 2 + khalf)) ^ (row & 7)) << 4); \
        asm volatile(                                                          \
          "ldmatrix.sync.aligned.m8n8.x4.shared.b16 {%0,%1,%2,%3}, [%4];"      \
          : "=r"(b[0]), "=r"(b[1]), "=r"(b[2]), "=r"(b[3])                     \
          : "r"(bd));                                                          \
      }                                                                        \
      _Pragma("unroll")                                                        \
      for (int mf = 0; mf < 4; ++mf) {                                         \
        _Pragma("unroll")                                                      \
        for (int nf = 0; nf < 2; ++nf) {                                       \
          asm volatile(                                                        \
            "mma.sync.aligned.m16n8k32.row.col.s32.s8.s8.s32 "                 \
            "{%0,%1,%2,%3}, {%4,%5,%6,%7}, {%8,%9}, {%0,%1,%2,%3};"            \
            : "+r"(ACC[mf][nf][0]), "+r"(ACC[mf][nf][1]),                      \
              "+r"(ACC[mf][nf][2]), "+r"(ACC[mf][nf][3])                       \
            : "r"(a[mf][0]), "r"(a[mf][1]), "r"(a[mf][2]), "r"(a[mf][3]),      \
              "r"(b[nf]), "r"(b[2 + nf]));                                     \
        }                                                                      \
      }                                                                        \
    }                                                                          \
  }

// dp4a path: bit-identical accumulation in mma c-fragment layout.
#define DP4A_CHUNK(ACC, SA)                                                    \
  {                                                                            \
    const uint32_t sA = (SA);                                                  \
    const uint32_t sB = sA + 16384u;                                           \
    _Pragma("unroll 2")                                                        \
    for (int kk = 0; kk < 8; ++kk) {                                           \
      uint32_t areg[8][4];                                                     \
      _Pragma("unroll")                                                        \
      for (int mf = 0; mf < 4; ++mf) {                                         \
        _Pragma("unroll")                                                      \
        for (int p = 0; p < 2; ++p) {                                          \
          const int row = wm * 64 + mf * 16 + p * 8 + (lane >> 2);             \
          const uint32_t ad = sA + (uint32_t)(row << 7)                        \
                            + (uint32_t)((kk ^ (row & 7)) << 4);               \
          asm volatile("ld.shared.v4.b32 {%0,%1,%2,%3}, [%4];"                 \
            : "=r"(areg[mf * 2 + p][0]), "=r"(areg[mf * 2 + p][1]),            \
              "=r"(areg[mf * 2 + p][2]), "=r"(areg[mf * 2 + p][3])             \
            : "r"(ad));                                                        \
        }                                                                      \
      }                                                                        \
      uint32_t breg[4][4];                                                     \
      _Pragma("unroll")                                                        \
      for (int nf = 0; nf < 2; ++nf) {                                         \
        _Pragma("unroll")                                                      \
        for (int d = 0; d < 2; ++d) {                                          \
          const int col = wn * 16 + nf * 8 + 2 * (lane & 3) + d;               \
          const uint32_t bd = sB + (uint32_t)(col << 7)                        \
                            + (uint32_t)((kk ^ (col & 7)) << 4);               \
          asm volatile("ld.shared.v4.b32 {%0,%1,%2,%3}, [%4];"                 \
            : "=r"(breg[nf * 2 + d][0]), "=r"(breg[nf * 2 + d][1]),            \
              "=r"(breg[nf * 2 + d][2]), "=r"(breg[nf * 2 + d][3])             \
            : "r"(bd));                                                        \
        }                                                                      \
      }                                                                        \
      _Pragma("unroll")                                                        \
      for (int mf = 0; mf < 4; ++mf) {                                         \
        _Pragma("unroll")                                                      \
        for (int nf = 0; nf < 2; ++nf) {                                       \
          _Pragma("unroll")                                                    \
          for (int e = 0; e < 4; ++e) {                                        \
            const int p = e >> 1, d = e & 1;                                   \
            _Pragma("unroll")                                                  \
            for (int w2 = 0; w2 < 4; ++w2)                                     \
              asm volatile("dp4a.s32.s32 %0, %1, %2, %0;"                      \
                : "+r"(ACC[mf][nf][e])                                         \
                : "r"(areg[mf * 2 + p][w2]), "r"(breg[nf * 2 + d][w2]));       \
          }                                                                    \
        }                                                                      \
      }                                                                        \
    }                                                                          \
  }

__global__ __launch_bounds__(256, 1)
void lstm_imma_kernel(const float* __restrict__ cx, float* __restrict__ out) {
    extern __shared__ char smem[];
    const uint32_t sb = smem_u32(smem);
    const int tid = threadIdx.x, lane = tid & 31, wid = tid >> 5;
    const int grp = wid >> 2;               // 0 = tensor, 1 = dp4a
    const int gt = tid & 127;               // index within group
    const int w = wid & 3;
    const int wm = w >> 1, wn = w & 1;
    const int m0 = blockIdx.y << 7, n0 = blockIdx.x << 5;
    const int rsel = lane & 15, khalf = lane >> 4;

    int* exch = reinterpret_cast<int*>(smem + EXCH_OFF);
    float* cx_sm = reinterpret_cast<float*>(smem + CX_OFF);
    float* h_sm = reinterpret_cast<float*>(smem + H_OFF);
    float* c_sm = reinterpret_cast<float*>(smem + C_OFF);

    int acc1[4][2][4], acc1b[4][2][4];
#pragma unroll
    for (int i = 0; i < 4; ++i)
#pragma unroll
        for (int j = 0; j < 2; ++j)
#pragma unroll
            for (int k = 0; k < 4; ++k) { acc1[i][j][k] = 0; acc1b[i][j][k] = 0; }

    if (grp == 0) {
        // -------- tensor group: chunks 0..34 (0-31 acc1, 32-34 acc1b) -------
        const uint32_t tb = sb + T_BASE;
        prefetch_chunk(tb, 0, 0, m0, n0, gt);
        asm volatile("cp.async.commit_group;");
        prefetch_chunk(tb, 1, 1, m0, n0, gt);
        asm volatile("cp.async.commit_group;");
        prefetch_chunk(tb, 2, 2, m0, n0, gt);
        asm volatile("cp.async.commit_group;");
        for (int j = 0; j < T_CH; ++j) {
            asm volatile("cp.async.wait_group 2;");
            asm volatile("bar.sync 1, 128;" ::: "memory");
            if (j + 3 < T_CH) prefetch_chunk(tb, (j + 3) & 3, j + 3, m0, n0, gt);
            asm volatile("cp.async.commit_group;");
            const uint32_t sa = tb + (uint32_t)((j & 3) * CHUNK_BYTES);
            if (j < 32) COMPUTE_CHUNK(acc1, sa) else COMPUTE_CHUNK(acc1b, sa)
        }
        asm volatile("cp.async.wait_group 0;");
    } else {
        // ---------------- dp4a group: chunks 35..47 -> acc2 ----------------
        int acc2[4][2][4];
#pragma unroll
        for (int i = 0; i < 4; ++i)
#pragma unroll
            for (int j = 0; j < 2; ++j)
#pragma unroll
                for (int k = 0; k < 4; ++k) acc2[i][j][k] = 0;
        const uint32_t db = sb + D_BASE;
        prefetch_chunk(db, 0, T_CH + 0, m0, n0, gt);
        asm volatile("cp.async.commit_group;");
        prefetch_chunk(db, 1, T_CH + 1, m0, n0, gt);
        asm volatile("cp.async.commit_group;");
        prefetch_chunk(db, 2, T_CH + 2, m0, n0, gt);
        asm volatile("cp.async.commit_group;");
        for (int j = 0; j < D_CH; ++j) {
            asm volatile("cp.async.wait_group 2;");
            asm volatile("bar.sync 2, 128;" ::: "memory");
            if (j + 3 < D_CH) prefetch_chunk(db, (j + 3) & 3, T_CH + j + 3, m0, n0, gt);
            asm volatile("cp.async.commit_group;");
            DP4A_CHUNK(acc2, db + (uint32_t)((j & 3) * CHUNK_BYTES))
        }
        asm volatile("cp.async.wait_group 0;");
        asm volatile("bar.sync 2, 128;" ::: "memory");
        // write acc2 to exchange buffer (stride 36 ints: conflict-free)
        int4* dst = reinterpret_cast<int4*>(exch + (w * 32 + lane) * 36);
#pragma unroll
        for (int mf = 0; mf < 4; ++mf)
#pragma unroll
            for (int nf = 0; nf < 2; ++nf)
                dst[mf * 2 + nf] = make_int4(acc2[mf][nf][0], acc2[mf][nf][1],
                                             acc2[mf][nf][2], acc2[mf][nf][3]);
    }

    __syncthreads();

    const int u0 = n0 >> 2;                  // 8 hidden units per tile
#pragma unroll
    for (int t = 0; t < 4; ++t) {
        const int idx = t * 256 + tid;
        const int r = idx >> 3, u = idx & 7;
        cx_sm[r * 9 + u] = cx[(size_t)(m0 + r) * H_DIM + u0 + u];
    }
    __syncthreads();

    if (grp == 0) {
        // combine + fused LSTM epilogue (tensor warps only)
        const int4* src = reinterpret_cast<const int4*>(exch + (w * 32 + lane) * 36);
        const float INV = 1.0f / 16129.0f;           // 1/127^2
        const float INV2 = 5.0f / 4129024.0f;        // 5/(127^2*256)
        const bool oddl = (lane & 1) != 0;
#pragma unroll
        for (int mf = 0; mf < 4; ++mf) {
#pragma unroll
            for (int nf = 0; nf < 2; ++nf) {
                const int4 sv = src[mf * 2 + nf];
                const int col0 = wn * 16 + nf * 8 + 2 * (lane & 3);
                const float bf0 = g_bias[n0 + col0];
                const float bf1 = g_bias[n0 + col0 + 1];
                float v0 = fmaf((float)acc1[mf][nf][0], INV,
                           fmaf((float)(acc1b[mf][nf][0] + sv.x), INV2, bf0));
                float v1 = fmaf((float)acc1[mf][nf][1], INV,
                           fmaf((float)(acc1b[mf][nf][1] + sv.y), INV2, bf1));
                float v2 = fmaf((float)acc1[mf][nf][2], INV,
                           fmaf((float)(acc1b[mf][nf][2] + sv.z), INV2, bf0));
                float v3 = fmaf((float)acc1[mf][nf][3], INV,
                           fmaf((float)(acc1b[mf][nf][3] + sv.w), INV2, bf1));
                float p0 = __shfl_xor_sync(0xFFFFFFFFu, v0, 1);
                float p1 = __shfl_xor_sync(0xFFFFFFFFu, v1, 1);
                float p2 = __shfl_xor_sync(0xFFFFFFFFu, v2, 1);
                float p3 = __shfl_xor_sync(0xFFFFFFFFu, v3, 1);
                const float gf = oddl ? p2 : v0;
                const float gi = oddl ? p3 : v1;
                const float gg = oddl ? v2 : p0;
                const float go = oddl ? v3 : p1;
                const int r = wm * 64 + mf * 16 + (lane >> 2) + (oddl ? 8 : 0);
                const int ul = wn * 4 + nf * 2 + ((lane & 3) >> 1);
                const float f = fq8(sigm_(gf));
                const float ii = fq8(sigm_(gi));
                const float gq = fq8(tanh_(gg));
                const float o = fq8(sigm_(go));
                const float cn = f * cx_sm[r * 9 + ul] + ii * gq;
                h_sm[r * 9 + ul] = o * fq8(tanh_(cn));
                c_sm[r * 9 + ul] = fq8(cn);
            }
        }
    }
    __syncthreads();

    float* hout = out;
    float* cout_ = out + (size_t)B_DIM * H_DIM;
#pragma unroll
    for (int t = 0; t < 4; ++t) {
        const int idx = t * 256 + tid;
        const int r = idx >> 3, u = idx & 7;
        hout[(size_t)(m0 + r) * H_DIM + u0 + u] = h_sm[r * 9 + u];
        cout_[(size_t)(m0 + r) * H_DIM + u0 + u] = c_sm[r * 9 + u];
    }
}

// ------------------------------- launcher ---------------------------------

extern "C" void kernel_launch(void* const* d_in, const int* in_sizes, int n_in,
                              void* d_out, int out_size) {
    (void)in_sizes; (void)n_in; (void)out_size;
    const float* x  = (const float*)d_in[0];
    const float* hx = (const float*)d_in[1];
    const float* cx = (const float*)d_in[2];
    const float* wx = (const float*)d_in[3];
    const float* bx = (const float*)d_in[4];
    const float* wh = (const float*)d_in[5];
    const float* bh = (const float*)d_in[6];
    float* out = (float*)d_out;

    cudaFuncSetAttribute(lstm_imma_kernel,
                         cudaFuncAttributeMaxDynamicSharedMemorySize, SMEM_BYTES);

    prep_A<<<dim3(2, B_DIM), 256>>>(x, hx);
    prep_W<<<dim3(6, NTOT), 256>>>(wx, wh);
    prep_bias<<<NTOT / 256, 256>>>(bx, bh);

    dim3 grid(NTOT / 32, B_DIM / 128);          // 256 x 8 = 2048 CTAs
    lstm_imma_kernel<<<grid, 256, SMEM_BYTES>>>(cx, out);
}

// round 10
// speedup vs baseline: 1.3507x; 1.3507x over previous
#include <cuda_runtime.h>
#include <cstdint>

#define B_DIM  1024
#define H_DIM  2048
#define KTOT   6144
#define NTOT   8192
#define NCH    48      // chunk ids: 0-15 x, 16-31 hi (acc1) ; 32-47 lo (acc2)
#define T_CH   29      // chunks 0..28  -> tensor (mma)
                       // chunks 29..47 -> dp4a   (29-31 acc1, 32-47 acc2)
#define STAGES 4
#define CHUNK_BYTES 20480            // A 16KB + B 4KB
#define SMEM_BYTES (STAGES * CHUNK_BYTES)   // 80KB

// h scale: S = 256*127/5; v = round(hx*S) in [-32511,32511]; v = hi*256 + lo
#define SCALE_H 6502.4f
#define VCLAMP  32511.0f

__device__ __align__(256) int8_t g_A[(size_t)B_DIM * KTOT];
__device__ __align__(256) int8_t g_B[(size_t)NTOT * KTOT];
__device__ float g_bias[NTOT];

// ------------------------------- helpers ----------------------------------

__device__ __forceinline__ uint32_t smem_u32(const void* p) {
    uint32_t a;
    asm("{ .reg .u64 t; cvta.to.shared.u64 t, %1; cvt.u32.u64 %0, t; }"
        : "=r"(a) : "l"(p));
    return a;
}

__device__ __forceinline__ float fq8(float v) {
    float q = rintf(v * 127.0f);
    q = fminf(127.0f, fmaxf(-127.0f, q));
    return q * (1.0f / 127.0f);
}

__device__ __forceinline__ float sigm_(float x) {
    return 1.0f / (1.0f + expf(-x));
}

__device__ __forceinline__ float tanh_(float x) {
    float e = expf(-2.0f * fabsf(x));
    return copysignf((1.0f - e) / (1.0f + e), x);
}

__device__ __forceinline__ signed char q127(float w) {
    float q = rintf(w * 127.0f);
    q = fminf(127.0f, fmaxf(-127.0f, q));
    return (signed char)(int)q;
}

// slot i -> chunk id; 29 tensor chunks + 19 dp4a chunks interleaved [t,t,d,t,d]
__device__ __forceinline__ int seq_chunk(int i) {
    if (i < 45) {
        const int g = i / 5, r = i % 5;
        if (r == 0) return 3 * g;
        if (r == 1) return 3 * g + 1;
        if (r == 2) return T_CH + 2 * g;
        if (r == 3) return 3 * g + 2;
        return T_CH + 2 * g + 1;
    }
    return (i == 45) ? 27 : (i == 46) ? 28 : 47;
}

// ------------------------------ prep kernels ------------------------------

__global__ void prep_A(const float* __restrict__ x, const float* __restrict__ hx) {
    const int b = blockIdx.y;
    const int c4 = blockIdx.x * 256 + threadIdx.x;      // 0..511
    const int k = c4 << 2;
    const float4 xv = *reinterpret_cast<const float4*>(x + (size_t)b * 2048 + k);
    const float4 hv = *reinterpret_cast<const float4*>(hx + (size_t)b * 2048 + k);
    const float* xf = reinterpret_cast<const float*>(&xv);
    const float* hf = reinterpret_cast<const float*>(&hv);
    char4 xq, hiq, loq;
    signed char* xp = reinterpret_cast<signed char*>(&xq);
    signed char* hp = reinterpret_cast<signed char*>(&hiq);
    signed char* lp = reinterpret_cast<signed char*>(&loq);
#pragma unroll
    for (int j = 0; j < 4; ++j) {
        xp[j] = q127(xf[j]);
        float vf = rintf(hf[j] * SCALE_H);
        vf = fminf(VCLAMP, fmaxf(-VCLAMP, vf));
        int v = (int)vf;
        int hi = (v + 128) >> 8;            // hi in [-127,127]
        int lo = v - (hi << 8);             // lo in [-128,127]
        hp[j] = (signed char)hi;
        lp[j] = (signed char)lo;
    }
    size_t base = (size_t)b * KTOT + k;
    *reinterpret_cast<char4*>(g_A + base)        = xq;
    *reinterpret_cast<char4*>(g_A + base + 2048) = hiq;
    *reinterpret_cast<char4*>(g_A + base + 4096) = loq;
}

// B row r=4u+g from orig row g*2048+u: [0,2048) wxI ; [2048,4096) whI*5 ; [4096,6144) whI
__global__ void prep_W(const float* __restrict__ wx, const float* __restrict__ wh) {
    const int r = blockIdx.y;
    const int c4 = blockIdx.x * 256 + threadIdx.x;      // 0..1535
    const int u = r >> 2, g = r & 3;
    const size_t orig = (size_t)(g * H_DIM + u) * 2048;
    char4 outv;
    signed char* op = reinterpret_cast<signed char*>(&outv);
    if (c4 < 512) {
        const float4 wv = *reinterpret_cast<const float4*>(wx + orig + (c4 << 2));
        const float* wf = reinterpret_cast<const float*>(&wv);
#pragma unroll
        for (int j = 0; j < 4; ++j) op[j] = q127(wf[j]);
    } else if (c4 < 1024) {
        const float4 wv = *reinterpret_cast<const float4*>(wh + orig + ((c4 - 512) << 2));
        const float* wf = reinterpret_cast<const float*>(&wv);
#pragma unroll
        for (int j = 0; j < 4; ++j) op[j] = (signed char)(5 * (int)q127(wf[j]));
    } else {
        const float4 wv = *reinterpret_cast<const float4*>(wh + orig + ((c4 - 1024) << 2));
        const float* wf = reinterpret_cast<const float*>(&wv);
#pragma unroll
        for (int j = 0; j < 4; ++j) op[j] = q127(wf[j]);
    }
    *reinterpret_cast<char4*>(g_B + (size_t)r * KTOT + (c4 << 2)) = outv;
}

__global__ void prep_bias(const float* __restrict__ bx, const float* __restrict__ bh) {
    int r = blockIdx.x * 256 + threadIdx.x;
    if (r >= NTOT) return;
    int u = r >> 2, g = r & 3;
    int orig = g * H_DIM + u;
    g_bias[r] = bx[orig] + bh[orig];
}

// ------------------------------- GEMM kernel ------------------------------
// CTA: 128(M) x 32(N), 128 threads, 4 warps (one per SMSP), 2 CTAs/SM.
// Warp tile: 64(M) x 16(N). Tensor chunks via mma, lo/overflow via dp4a.

__device__ __forceinline__ void prefetch_chunk(uint32_t sb, int stage, int chunk,
                                               int m0, int n0, int tid) {
    const int koff = chunk << 7;
    const uint32_t sbase = sb + (uint32_t)stage * CHUNK_BYTES;
#pragma unroll
    for (int p = 0; p < 10; ++p) {
        const int idx = p * 128 + tid;      // 0..1279 ; <1024 A, else B
        const bool isA = idx < 1024;
        const int v = isA ? idx : idx - 1024;
        const int row = v >> 3;
        const int q = v & 7;
        const uint32_t dst = sbase + (isA ? 0u : 16384u)
                           + (uint32_t)(row << 7)
                           + (uint32_t)((q ^ (row & 7)) << 4);
        const int8_t* src = isA
            ? g_A + (size_t)(m0 + row) * KTOT + koff + (q << 4)
            : g_B + (size_t)(n0 + row) * KTOT + koff + (q << 4);
        asm volatile("cp.async.cg.shared.global [%0], [%1], 16;"
                     :: "r"(dst), "l"(src));
    }
}

#define COMPUTE_CHUNK(ACC, SA)                                                 \
  {                                                                            \
    const uint32_t sA = (SA);                                                  \
    const uint32_t sB = sA + 16384u;                                           \
    _Pragma("unroll")                                                          \
    for (int ks = 0; ks < 4; ++ks) {                                           \
      uint32_t a[4][4], b[4];                                                  \
      _Pragma("unroll")                                                        \
      for (int mf = 0; mf < 4; ++mf) {                                         \
        const int row = wm * 64 + mf * 16 + rsel;                              \
        const uint32_t ad = sA + (uint32_t)(row << 7)                          \
                          + (uint32_t)((((ks * 2 + khalf)) ^ (row & 7)) << 4); \
        asm volatile(                                                          \
          "ldmatrix.sync.aligned.m8n8.x4.shared.b16 {%0,%1,%2,%3}, [%4];"      \
          : "=r"(a[mf][0]), "=r"(a[mf][1]), "=r"(a[mf][2]), "=r"(a[mf][3])     \
          : "r"(ad));                                                          \
      }                                                                        \
      {                                                                        \
        const int row = wn * 16 + rsel;                                        \
        const uint32_t bd = sB + (uint32_t)(row << 7)                          \
                          + (uint32_t)((((ks * 2 + khalf)) ^ (row & 7)) << 4); \
        asm volatile(                                                          \
          "ldmatrix.sync.aligned.m8n8.x4.shared.b16 {%0,%1,%2,%3}, [%4];"      \
          : "=r"(b[0]), "=r"(b[1]), "=r"(b[2]), "=r"(b[3])                     \
          : "r"(bd));                                                          \
      }                                                                        \
      _Pragma("unroll")                                                        \
      for (int mf = 0; mf < 4; ++mf) {                                         \
        _Pragma("unroll")                                                      \
        for (int nf = 0; nf < 2; ++nf) {                                       \
          asm volatile(                                                        \
            "mma.sync.aligned.m16n8k32.row.col.s32.s8.s8.s32 "                 \
            "{%0,%1,%2,%3}, {%4,%5,%6,%7}, {%8,%9}, {%0,%1,%2,%3};"            \
            : "+r"(ACC[mf][nf][0]), "+r"(ACC[mf][nf][1]),                      \
              "+r"(ACC[mf][nf][2]), "+r"(ACC[mf][nf][3])                       \
            : "r"(a[mf][0]), "r"(a[mf][1]), "r"(a[mf][2]), "r"(a[mf][3]),      \
              "r"(b[nf]), "r"(b[2 + nf]));                                     \
        }                                                                      \
      }                                                                        \
    }                                                                          \
  }

// dp4a path: bit-identical accumulation in mma c-fragment layout.
// w2 is the OUTERMOST MAC loop: 32 independent accumulators between reuses
// of the same register (R7 had w2 innermost -> 4-deep RAW chains -> ~2x slow).
#define DP4A_CHUNK(ACC, SA)                                                    \
  {                                                                            \
    const uint32_t sA = (SA);                                                  \
    const uint32_t sB = sA + 16384u;                                           \
    _Pragma("unroll 2")                                                        \
    for (int kk = 0; kk < 8; ++kk) {                                           \
      uint32_t areg[8][4];                                                     \
      _Pragma("unroll")                                                        \
      for (int mf = 0; mf < 4; ++mf) {                                         \
        _Pragma("unroll")                                                      \
        for (int p = 0; p < 2; ++p) {                                          \
          const int row = wm * 64 + mf * 16 + p * 8 + (lane >> 2);             \
          const uint32_t ad = sA + (uint32_t)(row << 7)                        \
                            + (uint32_t)((kk ^ (row & 7)) << 4);               \
          asm volatile("ld.shared.v4.b32 {%0,%1,%2,%3}, [%4];"                 \
            : "=r"(areg[mf * 2 + p][0]), "=r"(areg[mf * 2 + p][1]),            \
              "=r"(areg[mf * 2 + p][2]), "=r"(areg[mf * 2 + p][3])             \
            : "r"(ad));                                                        \
        }                                                                      \
      }                                                                        \
      uint32_t breg[4][4];                                                     \
      _Pragma("unroll")                                                        \
      for (int nf = 0; nf < 2; ++nf) {                                         \
        _Pragma("unroll")                                                      \
        for (int d = 0; d < 2; ++d) {                                          \
          const int col = wn * 16 + nf * 8 + 2 * (lane & 3) + d;               \
          const uint32_t bd = sB + (uint32_t)(col << 7)                        \
                            + (uint32_t)((kk ^ (col & 7)) << 4);               \
          asm volatile("ld.shared.v4.b32 {%0,%1,%2,%3}, [%4];"                 \
            : "=r"(breg[nf * 2 + d][0]), "=r"(breg[nf * 2 + d][1]),            \
              "=r"(breg[nf * 2 + d][2]), "=r"(breg[nf * 2 + d][3])             \
            : "r"(bd));                                                        \
        }                                                                      \
      }                                                                        \
      _Pragma("unroll")                                                        \
      for (int w2 = 0; w2 < 4; ++w2) {                                         \
        _Pragma("unroll")                                                      \
        for (int mf = 0; mf < 4; ++mf) {                                       \
          _Pragma("unroll")                                                    \
          for (int nf = 0; nf < 2; ++nf) {                                     \
            _Pragma("unroll")                                                  \
            for (int e = 0; e < 4; ++e) {                                      \
              const int p = e >> 1, d = e & 1;                                 \
              asm volatile("dp4a.s32.s32 %0, %1, %2, %0;"                      \
                : "+r"(ACC[mf][nf][e])                                         \
                : "r"(areg[mf * 2 + p][w2]), "r"(breg[nf * 2 + d][w2]));       \
            }                                                                  \
          }                                                                    \
        }                                                                      \
      }                                                                        \
    }                                                                          \
  }

__global__ __launch_bounds__(128, 2)
void lstm_imma_kernel(const float* __restrict__ cx, float* __restrict__ out) {
    extern __shared__ char smem[];
    const uint32_t sb = smem_u32(smem);
    const int tid = threadIdx.x, lane = tid & 31, wid = tid >> 5;
    const int wm = wid >> 1, wn = wid & 1;
    const int m0 = blockIdx.y << 7, n0 = blockIdx.x << 5;
    const int rsel = lane & 15, khalf = lane >> 4;

    int acc1[4][2][4], acc2[4][2][4];
#pragma unroll
    for (int i = 0; i < 4; ++i)
#pragma unroll
        for (int j = 0; j < 2; ++j)
#pragma unroll
            for (int k = 0; k < 4; ++k) { acc1[i][j][k] = 0; acc2[i][j][k] = 0; }

    prefetch_chunk(sb, 0, seq_chunk(0), m0, n0, tid);
    asm volatile("cp.async.commit_group;");
    prefetch_chunk(sb, 1, seq_chunk(1), m0, n0, tid);
    asm volatile("cp.async.commit_group;");
    prefetch_chunk(sb, 2, seq_chunk(2), m0, n0, tid);
    asm volatile("cp.async.commit_group;");

    for (int i = 0; i < NCH; ++i) {
        asm volatile("cp.async.wait_group 2;");
        __syncthreads();
        if (i + 3 < NCH) prefetch_chunk(sb, (i + 3) & 3, seq_chunk(i + 3), m0, n0, tid);
        asm volatile("cp.async.commit_group;");
        const uint32_t sa = sb + (uint32_t)((i & 3) * CHUNK_BYTES);
        const int c = seq_chunk(i);
        if (c < T_CH) {
            COMPUTE_CHUNK(acc1, sa)
        } else if (c < 32) {
            DP4A_CHUNK(acc1, sa)          // hi-region overflow chunks, INV scale
        } else {
            DP4A_CHUNK(acc2, sa)          // lo-region chunks, INV2 scale
        }
    }
    asm volatile("cp.async.wait_group 0;");
    __syncthreads();

    // ---------------- fused LSTM epilogue ----------------
    float* cx_sm = reinterpret_cast<float*>(smem);        // 128 x 9
    float* h_sm = cx_sm + 128 * 9;
    float* c_sm = h_sm + 128 * 9;
    const int u0 = n0 >> 2;                                // 8 units per tile
#pragma unroll
    for (int t = 0; t < 8; ++t) {
        const int idx = t * 128 + tid;
        const int r = idx >> 3, u = idx & 7;
        cx_sm[r * 9 + u] = cx[(size_t)(m0 + r) * H_DIM + u0 + u];
    }
    __syncthreads();

    const float INV = 1.0f / 16129.0f;              // 1/127^2
    const float INV2 = 5.0f / 4129024.0f;           // 1/(127*S) = 5/(127^2*256)
    const bool oddl = (lane & 1) != 0;
#pragma unroll
    for (int mf = 0; mf < 4; ++mf) {
#pragma unroll
        for (int nf = 0; nf < 2; ++nf) {
            const int col0 = wn * 16 + nf * 8 + 2 * (lane & 3);
            const float bf0 = g_bias[n0 + col0];
            const float bf1 = g_bias[n0 + col0 + 1];
            float v0 = fmaf((float)acc1[mf][nf][0], INV,
                       fmaf((float)acc2[mf][nf][0], INV2, bf0));
            float v1 = fmaf((float)acc1[mf][nf][1], INV,
                       fmaf((float)acc2[mf][nf][1], INV2, bf1));
            float v2 = fmaf((float)acc1[mf][nf][2], INV,
                       fmaf((float)acc2[mf][nf][2], INV2, bf0));
            float v3 = fmaf((float)acc1[mf][nf][3], INV,
                       fmaf((float)acc2[mf][nf][3], INV2, bf1));
            float p0 = __shfl_xor_sync(0xFFFFFFFFu, v0, 1);
            float p1 = __shfl_xor_sync(0xFFFFFFFFu, v1, 1);
            float p2 = __shfl_xor_sync(0xFFFFFFFFu, v2, 1);
            float p3 = __shfl_xor_sync(0xFFFFFFFFu, v3, 1);
            const float gf = oddl ? p2 : v0;
            const float gi = oddl ? p3 : v1;
            const float gg = oddl ? v2 : p0;
            const float go = oddl ? v3 : p1;
            const int r = wm * 64 + mf * 16 + (lane >> 2) + (oddl ? 8 : 0);
            const int ul = wn * 4 + nf * 2 + ((lane & 3) >> 1);
            const float f = fq8(sigm_(gf));
            const float ii = fq8(sigm_(gi));
            const float gq = fq8(tanh_(gg));
            const float o = fq8(sigm_(go));
            const float cn = f * cx_sm[r * 9 + ul] + ii * gq;
            h_sm[r * 9 + ul] = o * fq8(tanh_(cn));
            c_sm[r * 9 + ul] = fq8(cn);
        }
    }
    __syncthreads();

    float* hout = out;
    float* cout_ = out + (size_t)B_DIM * H_DIM;
#pragma unroll
    for (int t = 0; t < 8; ++t) {
        const int idx = t * 128 + tid;
        const int r = idx >> 3, u = idx & 7;
        hout[(size_t)(m0 + r) * H_DIM + u0 + u] = h_sm[r * 9 + u];
        cout_[(size_t)(m0 + r) * H_DIM + u0 + u] = c_sm[r * 9 + u];
    }
}

// ------------------------------- launcher ---------------------------------

extern "C" void kernel_launch(void* const* d_in, const int* in_sizes, int n_in,
                              void* d_out, int out_size) {
    (void)in_sizes; (void)n_in; (void)out_size;
    const float* x  = (const float*)d_in[0];
    const float* hx = (const float*)d_in[1];
    const float* cx = (const float*)d_in[2];
    const float* wx = (const float*)d_in[3];
    const float* bx = (const float*)d_in[4];
    const float* wh = (const float*)d_in[5];
    const float* bh = (const float*)d_in[6];
    float* out = (float*)d_out;

    cudaFuncSetAttribute(lstm_imma_kernel,
                         cudaFuncAttributeMaxDynamicSharedMemorySize, SMEM_BYTES);

    prep_A<<<dim3(2, B_DIM), 256>>>(x, hx);
    prep_W<<<dim3(6, NTOT), 256>>>(wx, wh);
    prep_bias<<<NTOT / 256, 256>>>(bx, bh);

    dim3 grid(NTOT / 32, B_DIM / 128);          // 256 x 8 = 2048 CTAs
    lstm_imma_kernel<<<grid, 128, SMEM_BYTES>>>(cx, out);
}

// round 11
// speedup vs baseline: 2.1912x; 1.6223x over previous
#include <cuda_runtime.h>
#include <cuda_bf16.h>
#include <cstdint>

#define B_DIM  1024
#define H_DIM  2048
#define KTOT   6144
#define NTOT   8192
#define NCH    96      // K-chunks of 64 bf16: 0-31 x, 32-63 hi (acc1); 64-95 lo (acc2)
#define STAGES 4
#define CHUNK_BYTES 20480            // A 128x64x2 = 16KB + B 32x64x2 = 4KB
#define SMEM_BYTES (STAGES * CHUNK_BYTES)   // 80KB

// h scale: S = 256*127/5; v = round(hx*S) in [-32511,32511]; v = hi*256 + lo
#define SCALE_H 6502.4f
#define VCLAMP  32511.0f

__device__ __align__(256) __nv_bfloat16 g_A[(size_t)B_DIM * KTOT];
__device__ __align__(256) __nv_bfloat16 g_B[(size_t)NTOT * KTOT];
__device__ float g_bias[NTOT];

// ------------------------------- helpers ----------------------------------

__device__ __forceinline__ uint32_t smem_u32(const void* p) {
    uint32_t a;
    asm("{ .reg .u64 t; cvta.to.shared.u64 t, %1; cvt.u32.u64 %0, t; }"
        : "=r"(a) : "l"(p));
    return a;
}

__device__ __forceinline__ float fq8(float v) {
    float q = rintf(v * 127.0f);
    q = fminf(127.0f, fmaxf(-127.0f, q));
    return q * (1.0f / 127.0f);
}

__device__ __forceinline__ float sigm_(float x) {
    return 1.0f / (1.0f + expf(-x));
}

__device__ __forceinline__ float tanh_(float x) {
    float e = expf(-2.0f * fabsf(x));
    return copysignf((1.0f - e) / (1.0f + e), x);
}

__device__ __forceinline__ float q127f(float w) {
    float q = rintf(w * 127.0f);
    return fminf(127.0f, fmaxf(-127.0f, q));
}

// ------------------------------ prep kernels ------------------------------
// A[1024][6144] bf16: [0,2048) xI ; [2048,4096) hi ; [4096,6144) lo
// All values are small integers -> exact in bf16.
__global__ void prep_A(const float* __restrict__ x, const float* __restrict__ hx) {
    const int b = blockIdx.y;
    const int c4 = blockIdx.x * 256 + threadIdx.x;      // 0..511
    const int k = c4 << 2;
    const float4 xv = *reinterpret_cast<const float4*>(x + (size_t)b * 2048 + k);
    const float4 hv = *reinterpret_cast<const float4*>(hx + (size_t)b * 2048 + k);
    const float* xf = reinterpret_cast<const float*>(&xv);
    const float* hf = reinterpret_cast<const float*>(&hv);
    ushort4 xq, hiq, loq;
    unsigned short* xp = reinterpret_cast<unsigned short*>(&xq);
    unsigned short* hp = reinterpret_cast<unsigned short*>(&hiq);
    unsigned short* lp = reinterpret_cast<unsigned short*>(&loq);
#pragma unroll
    for (int j = 0; j < 4; ++j) {
        xp[j] = __bfloat16_as_ushort(__float2bfloat16_rn(q127f(xf[j])));
        float vf = rintf(hf[j] * SCALE_H);
        vf = fminf(VCLAMP, fmaxf(-VCLAMP, vf));
        int v = (int)vf;
        int hi = (v + 128) >> 8;            // hi in [-127,127]
        int lo = v - (hi << 8);             // lo in [-128,127]
        hp[j] = __bfloat16_as_ushort(__float2bfloat16_rn((float)hi));
        lp[j] = __bfloat16_as_ushort(__float2bfloat16_rn((float)lo));
    }
    size_t base = (size_t)b * KTOT + k;
    *reinterpret_cast<ushort4*>(g_A + base)        = xq;
    *reinterpret_cast<ushort4*>(g_A + base + 2048) = hiq;
    *reinterpret_cast<ushort4*>(g_A + base + 4096) = loq;
}

// B row r=4u+g from orig row g*2048+u: [0,2048) wxI ; [2048,4096) whI*5 ; [4096,6144) whI
__global__ void prep_W(const float* __restrict__ wx, const float* __restrict__ wh) {
    const int r = blockIdx.y;
    const int c4 = blockIdx.x * 256 + threadIdx.x;      // 0..1535
    const int u = r >> 2, g = r & 3;
    const size_t orig = (size_t)(g * H_DIM + u) * 2048;
    ushort4 outv;
    unsigned short* op = reinterpret_cast<unsigned short*>(&outv);
    if (c4 < 512) {
        const float4 wv = *reinterpret_cast<const float4*>(wx + orig + (c4 << 2));
        const float* wf = reinterpret_cast<const float*>(&wv);
#pragma unroll
        for (int j = 0; j < 4; ++j)
            op[j] = __bfloat16_as_ushort(__float2bfloat16_rn(q127f(wf[j])));
    } else if (c4 < 1024) {
        const float4 wv = *reinterpret_cast<const float4*>(wh + orig + ((c4 - 512) << 2));
        const float* wf = reinterpret_cast<const float*>(&wv);
#pragma unroll
        for (int j = 0; j < 4; ++j)
            op[j] = __bfloat16_as_ushort(__float2bfloat16_rn(5.0f * q127f(wf[j])));
    } else {
        const float4 wv = *reinterpret_cast<const float4*>(wh + orig + ((c4 - 1024) << 2));
        const float* wf = reinterpret_cast<const float*>(&wv);
#pragma unroll
        for (int j = 0; j < 4; ++j)
            op[j] = __bfloat16_as_ushort(__float2bfloat16_rn(q127f(wf[j])));
    }
    *reinterpret_cast<ushort4*>(g_B + (size_t)r * KTOT + (c4 << 2)) = outv;
}

__global__ void prep_bias(const float* __restrict__ bx, const float* __restrict__ bh) {
    int r = blockIdx.x * 256 + threadIdx.x;
    if (r >= NTOT) return;
    int u = r >> 2, g = r & 3;
    int orig = g * H_DIM + u;
    g_bias[r] = bx[orig] + bh[orig];
}

// ------------------------------- GEMM kernel ------------------------------
// CTA: 128(M) x 32(N), 128 threads, 4 warps, 2 CTAs/SM.
// bf16 m16n8k16 HMMA, fp32 accumulators (exact integer accumulation).

__device__ __forceinline__ void prefetch_chunk(uint32_t sb, int stage, int chunk,
                                               int m0, int n0, int tid) {
    const int koff = chunk << 6;        // 64 bf16 per chunk
    const uint32_t sbase = sb + (uint32_t)stage * CHUNK_BYTES;
#pragma unroll
    for (int p = 0; p < 10; ++p) {
        const int idx = p * 128 + tid;      // 0..1279 ; <1024 A, else B
        const bool isA = idx < 1024;
        const int v = isA ? idx : idx - 1024;
        const int row = v >> 3;
        const int q = v & 7;
        const uint32_t dst = sbase + (isA ? 0u : 16384u)
                           + (uint32_t)(row << 7)
                           + (uint32_t)((q ^ (row & 7)) << 4);
        const __nv_bfloat16* src = isA
            ? g_A + (size_t)(m0 + row) * KTOT + koff + (q << 3)
            : g_B + (size_t)(n0 + row) * KTOT + koff + (q << 3);
        asm volatile("cp.async.cg.shared.global [%0], [%1], 16;"
                     :: "r"(dst), "l"(src));
    }
}

#define COMPUTE_CHUNK(ACC, SA)                                                 \
  {                                                                            \
    const uint32_t sA = (SA);                                                  \
    const uint32_t sB = sA + 16384u;                                           \
    _Pragma("unroll")                                                          \
    for (int ks = 0; ks < 4; ++ks) {                                           \
      uint32_t a[4][4], b[4];                                                  \
      _Pragma("unroll")                                                        \
      for (int mf = 0; mf < 4; ++mf) {                                         \
        const int row = wm * 64 + mf * 16 + rsel;                              \
        const uint32_t ad = sA + (uint32_t)(row << 7)                          \
                          + (uint32_t)((((ks * 2 + khalf)) ^ (row & 7)) << 4); \
        asm volatile(                                                          \
          "ldmatrix.sync.aligned.m8n8.x4.shared.b16 {%0,%1,%2,%3}, [%4];"      \
          : "=r"(a[mf][0]), "=r"(a[mf][1]), "=r"(a[mf][2]), "=r"(a[mf][3])     \
          : "r"(ad));                                                          \
      }                                                                        \
      {                                                                        \
        const int row = wn * 16 + rsel;                                        \
        const uint32_t bd = sB + (uint32_t)(row << 7)                          \
                          + (uint32_t)((((ks * 2 + khalf)) ^ (row & 7)) << 4); \
        asm volatile(                                                          \
          "ldmatrix.sync.aligned.m8n8.x4.shared.b16 {%0,%1,%2,%3}, [%4];"      \
          : "=r"(b[0]), "=r"(b[1]), "=r"(b[2]), "=r"(b[3])                     \
          : "r"(bd));                                                          \
      }                                                                        \
      _Pragma("unroll")                                                        \
      for (int mf = 0; mf < 4; ++mf) {                                         \
        _Pragma("unroll")                                                      \
        for (int nf = 0; nf < 2; ++nf) {                                       \
          asm volatile(                                                        \
            "mma.sync.aligned.m16n8k16.row.col.f32.bf16.bf16.f32 "             \
            "{%0,%1,%2,%3}, {%4,%5,%6,%7}, {%8,%9}, {%0,%1,%2,%3};"            \
            : "+f"(ACC[mf][nf][0]), "+f"(ACC[mf][nf][1]),                      \
              "+f"(ACC[mf][nf][2]), "+f"(ACC[mf][nf][3])                       \
            : "r"(a[mf][0]), "r"(a[mf][1]), "r"(a[mf][2]), "r"(a[mf][3]),      \
              "r"(b[nf]), "r"(b[2 + nf]));                                     \
        }                                                                      \
      }                                                                        \
    }                                                                          \
  }

__global__ __launch_bounds__(128, 2)
void lstm_hmma_kernel(const float* __restrict__ cx, float* __restrict__ out) {
    extern __shared__ char smem[];
    const uint32_t sb = smem_u32(smem);
    const int tid = threadIdx.x, lane = tid & 31, wid = tid >> 5;
    const int wm = wid >> 1, wn = wid & 1;
    const int m0 = blockIdx.y << 7, n0 = blockIdx.x << 5;
    const int rsel = lane & 15, khalf = lane >> 4;

    float acc1[4][2][4], acc2[4][2][4];
#pragma unroll
    for (int i = 0; i < 4; ++i)
#pragma unroll
        for (int j = 0; j < 2; ++j)
#pragma unroll
            for (int k = 0; k < 4; ++k) { acc1[i][j][k] = 0.0f; acc2[i][j][k] = 0.0f; }

    prefetch_chunk(sb, 0, 0, m0, n0, tid);
    asm volatile("cp.async.commit_group;");
    prefetch_chunk(sb, 1, 1, m0, n0, tid);
    asm volatile("cp.async.commit_group;");
    prefetch_chunk(sb, 2, 2, m0, n0, tid);
    asm volatile("cp.async.commit_group;");

    for (int i = 0; i < NCH; ++i) {
        asm volatile("cp.async.wait_group 2;");
        __syncthreads();
        if (i + 3 < NCH) prefetch_chunk(sb, (i + 3) & 3, i + 3, m0, n0, tid);
        asm volatile("cp.async.commit_group;");
        const uint32_t sa = sb + (uint32_t)((i & 3) * CHUNK_BYTES);
        if (i < 64) COMPUTE_CHUNK(acc1, sa) else COMPUTE_CHUNK(acc2, sa)
    }
    asm volatile("cp.async.wait_group 0;");
    __syncthreads();

    // ---------------- fused LSTM epilogue ----------------
    float* cx_sm = reinterpret_cast<float*>(smem);        // 128 x 9
    float* h_sm = cx_sm + 128 * 9;
    float* c_sm = h_sm + 128 * 9;
    const int u0 = n0 >> 2;                                // 8 units per tile
#pragma unroll
    for (int t = 0; t < 8; ++t) {
        const int idx = t * 128 + tid;
        const int r = idx >> 3, u = idx & 7;
        cx_sm[r * 9 + u] = cx[(size_t)(m0 + r) * H_DIM + u0 + u];
    }
    __syncthreads();

    const float INV = 1.0f / 16129.0f;              // 1/127^2
    const float INV2 = 5.0f / 4129024.0f;           // 1/(127*S) = 5/(127^2*256)
    const bool oddl = (lane & 1) != 0;
#pragma unroll
    for (int mf = 0; mf < 4; ++mf) {
#pragma unroll
        for (int nf = 0; nf < 2; ++nf) {
            const int col0 = wn * 16 + nf * 8 + 2 * (lane & 3);
            const float bf0 = g_bias[n0 + col0];
            const float bf1 = g_bias[n0 + col0 + 1];
            float v0 = fmaf(acc1[mf][nf][0], INV, fmaf(acc2[mf][nf][0], INV2, bf0));
            float v1 = fmaf(acc1[mf][nf][1], INV, fmaf(acc2[mf][nf][1], INV2, bf1));
            float v2 = fmaf(acc1[mf][nf][2], INV, fmaf(acc2[mf][nf][2], INV2, bf0));
            float v3 = fmaf(acc1[mf][nf][3], INV, fmaf(acc2[mf][nf][3], INV2, bf1));
            float p0 = __shfl_xor_sync(0xFFFFFFFFu, v0, 1);
            float p1 = __shfl_xor_sync(0xFFFFFFFFu, v1, 1);
            float p2 = __shfl_xor_sync(0xFFFFFFFFu, v2, 1);
            float p3 = __shfl_xor_sync(0xFFFFFFFFu, v3, 1);
            const float gf = oddl ? p2 : v0;
            const float gi = oddl ? p3 : v1;
            const float gg = oddl ? v2 : p0;
            const float go = oddl ? v3 : p1;
            const int r = wm * 64 + mf * 16 + (lane >> 2) + (oddl ? 8 : 0);
            const int ul = wn * 4 + nf * 2 + ((lane & 3) >> 1);
            const float f = fq8(sigm_(gf));
            const float ii = fq8(sigm_(gi));
            const float gq = fq8(tanh_(gg));
            const float o = fq8(sigm_(go));
            const float cn = f * cx_sm[r * 9 + ul] + ii * gq;
            h_sm[r * 9 + ul] = o * fq8(tanh_(cn));
            c_sm[r * 9 + ul] = fq8(cn);
        }
    }
    __syncthreads();

    float* hout = out;
    float* cout_ = out + (size_t)B_DIM * H_DIM;
#pragma unroll
    for (int t = 0; t < 8; ++t) {
        const int idx = t * 128 + tid;
        const int r = idx >> 3, u = idx & 7;
        hout[(size_t)(m0 + r) * H_DIM + u0 + u] = h_sm[r * 9 + u];
        cout_[(size_t)(m0 + r) * H_DIM + u0 + u] = c_sm[r * 9 + u];
    }
}

// ------------------------------- launcher ---------------------------------

extern "C" void kernel_launch(void* const* d_in, const int* in_sizes, int n_in,
                              void* d_out, int out_size) {
    (void)in_sizes; (void)n_in; (void)out_size;
    const float* x  = (const float*)d_in[0];
    const float* hx = (const float*)d_in[1];
    const float* cx = (const float*)d_in[2];
    const float* wx = (const float*)d_in[3];
    const float* bx = (const float*)d_in[4];
    const float* wh = (const float*)d_in[5];
    const float* bh = (const float*)d_in[6];
    float* out = (float*)d_out;

    cudaFuncSetAttribute(lstm_hmma_kernel,
                         cudaFuncAttributeMaxDynamicSharedMemorySize, SMEM_BYTES);

    prep_A<<<dim3(2, B_DIM), 256>>>(x, hx);
    prep_W<<<dim3(6, NTOT), 256>>>(wx, wh);
    prep_bias<<<NTOT / 256, 256>>>(bx, bh);

    dim3 grid(NTOT / 32, B_DIM / 128);          // 256 x 8 = 2048 CTAs
    lstm_hmma_kernel<<<grid, 128, SMEM_BYTES>>>(cx, out);
}

// round 12
// speedup vs baseline: 2.5475x; 1.1626x over previous
#include <cuda_runtime.h>
#include <cuda_bf16.h>
#include <cstdint>

#define B_DIM  1024
#define H_DIM  2048
#define KTOT   6144
#define NTOT   8192
#define NCH    96      // K-chunks of 64 bf16: 0-63 (x|hi) -> acc1 ; 64-95 lo -> acc2
#define STAGES 4
#define CHUNK_BYTES 24576            // A 128x64x2 = 16KB + B 64x64x2 = 8KB
#define SMEM_BYTES (STAGES * CHUNK_BYTES)   // 96KB

// h scale: S = 256*127/5; v = round(hx*S) in [-32511,32511]; v = hi*256 + lo
#define SCALE_H 6502.4f
#define VCLAMP  32511.0f

__device__ __align__(256) __nv_bfloat16 g_A[(size_t)B_DIM * KTOT];
__device__ __align__(256) __nv_bfloat16 g_B[(size_t)NTOT * KTOT];
__device__ float g_bias[NTOT];

// ------------------------------- helpers ----------------------------------

__device__ __forceinline__ uint32_t smem_u32(const void* p) {
    uint32_t a;
    asm("{ .reg .u64 t; cvta.to.shared.u64 t, %1; cvt.u32.u64 %0, t; }"
        : "=r"(a) : "l"(p));
    return a;
}

__device__ __forceinline__ float fq8(float v) {
    float q = rintf(v * 127.0f);
    q = fminf(127.0f, fmaxf(-127.0f, q));
    return q * (1.0f / 127.0f);
}

__device__ __forceinline__ float sigm_(float x) {
    return 1.0f / (1.0f + expf(-x));
}

__device__ __forceinline__ float tanh_(float x) {
    float e = expf(-2.0f * fabsf(x));
    return copysignf((1.0f - e) / (1.0f + e), x);
}

__device__ __forceinline__ float q127f(float w) {
    float q = rintf(w * 127.0f);
    return fminf(127.0f, fmaxf(-127.0f, q));
}

// ------------------------------ prep kernels ------------------------------

__global__ void prep_A(const float* __restrict__ x, const float* __restrict__ hx) {
    const int b = blockIdx.y;
    const int c4 = blockIdx.x * 256 + threadIdx.x;      // 0..511
    const int k = c4 << 2;
    const float4 xv = *reinterpret_cast<const float4*>(x + (size_t)b * 2048 + k);
    const float4 hv = *reinterpret_cast<const float4*>(hx + (size_t)b * 2048 + k);
    const float* xf = reinterpret_cast<const float*>(&xv);
    const float* hf = reinterpret_cast<const float*>(&hv);
    ushort4 xq, hiq, loq;
    unsigned short* xp = reinterpret_cast<unsigned short*>(&xq);
    unsigned short* hp = reinterpret_cast<unsigned short*>(&hiq);
    unsigned short* lp = reinterpret_cast<unsigned short*>(&loq);
#pragma unroll
    for (int j = 0; j < 4; ++j) {
        xp[j] = __bfloat16_as_ushort(__float2bfloat16_rn(q127f(xf[j])));
        float vf = rintf(hf[j] * SCALE_H);
        vf = fminf(VCLAMP, fmaxf(-VCLAMP, vf));
        int v = (int)vf;
        int hi = (v + 128) >> 8;            // hi in [-127,127]
        int lo = v - (hi << 8);             // lo in [-128,127]
        hp[j] = __bfloat16_as_ushort(__float2bfloat16_rn((float)hi));
        lp[j] = __bfloat16_as_ushort(__float2bfloat16_rn((float)lo));
    }
    size_t base = (size_t)b * KTOT + k;
    *reinterpret_cast<ushort4*>(g_A + base)        = xq;
    *reinterpret_cast<ushort4*>(g_A + base + 2048) = hiq;
    *reinterpret_cast<ushort4*>(g_A + base + 4096) = loq;
}

// B row r=4u+g from orig row g*2048+u: [0,2048) wxI ; [2048,4096) whI*5 ; [4096,6144) whI
__global__ void prep_W(const float* __restrict__ wx, const float* __restrict__ wh) {
    const int r = blockIdx.y;
    const int c4 = blockIdx.x * 256 + threadIdx.x;      // 0..1535
    const int u = r >> 2, g = r & 3;
    const size_t orig = (size_t)(g * H_DIM + u) * 2048;
    ushort4 outv;
    unsigned short* op = reinterpret_cast<unsigned short*>(&outv);
    if (c4 < 512) {
        const float4 wv = *reinterpret_cast<const float4*>(wx + orig + (c4 << 2));
        const float* wf = reinterpret_cast<const float*>(&wv);
#pragma unroll
        for (int j = 0; j < 4; ++j)
            op[j] = __bfloat16_as_ushort(__float2bfloat16_rn(q127f(wf[j])));
    } else if (c4 < 1024) {
        const float4 wv = *reinterpret_cast<const float4*>(wh + orig + ((c4 - 512) << 2));
        const float* wf = reinterpret_cast<const float*>(&wv);
#pragma unroll
        for (int j = 0; j < 4; ++j)
            op[j] = __bfloat16_as_ushort(__float2bfloat16_rn(5.0f * q127f(wf[j])));
    } else {
        const float4 wv = *reinterpret_cast<const float4*>(wh + orig + ((c4 - 1024) << 2));
        const float* wf = reinterpret_cast<const float*>(&wv);
#pragma unroll
        for (int j = 0; j < 4; ++j)
            op[j] = __bfloat16_as_ushort(__float2bfloat16_rn(q127f(wf[j])));
    }
    *reinterpret_cast<ushort4*>(g_B + (size_t)r * KTOT + (c4 << 2)) = outv;
}

__global__ void prep_bias(const float* __restrict__ bx, const float* __restrict__ bh) {
    int r = blockIdx.x * 256 + threadIdx.x;
    if (r >= NTOT) return;
    int u = r >> 2, g = r & 3;
    int orig = g * H_DIM + u;
    g_bias[r] = bx[orig] + bh[orig];
}

// ------------------------------- GEMM kernel ------------------------------
// CTA: 128(M) x 64(N), 128 threads, 4 warps (wm,wn in {0,1}), 2 CTAs/SM.
// Warp tile: 64(M) x 32(N). bf16 m16n8k16 HMMA, fp32 accumulators.

__device__ __forceinline__ void prefetch_chunk(uint32_t sb, int stage, int chunk,
                                               int m0, int n0, int tid) {
    const int koff = chunk << 6;        // 64 bf16 per chunk
    const uint32_t sbase = sb + (uint32_t)stage * CHUNK_BYTES;
#pragma unroll
    for (int p = 0; p < 12; ++p) {
        const int idx = p * 128 + tid;      // 0..1535 ; <1024 A, else B
        const bool isA = idx < 1024;
        const int v = isA ? idx : idx - 1024;
        const int row = v >> 3;
        const int q = v & 7;
        const uint32_t dst = sbase + (isA ? 0u : 16384u)
                           + (uint32_t)(row << 7)
                           + (uint32_t)((q ^ (row & 7)) << 4);
        const __nv_bfloat16* src = isA
            ? g_A + (size_t)(m0 + row) * KTOT + koff + (q << 3)
            : g_B + (size_t)(n0 + row) * KTOT + koff + (q << 3);
        asm volatile("cp.async.cg.shared.global [%0], [%1], 16;"
                     :: "r"(dst), "l"(src));
    }
}

#define COMPUTE_CHUNK(ACC, SA)                                                 \
  {                                                                            \
    const uint32_t sA = (SA);                                                  \
    const uint32_t sB = sA + 16384u;                                           \
    _Pragma("unroll")                                                          \
    for (int ks = 0; ks < 4; ++ks) {                                           \
      uint32_t a[4][4], b[2][4];                                               \
      _Pragma("unroll")                                                        \
      for (int mf = 0; mf < 4; ++mf) {                                         \
        const int row = wm * 64 + mf * 16 + rsel;                              \
        const uint32_t ad = sA + (uint32_t)(row << 7)                          \
                          + (uint32_t)((((ks * 2 + khalf)) ^ (row & 7)) << 4); \
        asm volatile(                                                          \
          "ldmatrix.sync.aligned.m8n8.x4.shared.b16 {%0,%1,%2,%3}, [%4];"      \
          : "=r"(a[mf][0]), "=r"(a[mf][1]), "=r"(a[mf][2]), "=r"(a[mf][3])     \
          : "r"(ad));                                                          \
      }                                                                        \
      _Pragma("unroll")                                                        \
      for (int np = 0; np < 2; ++np) {                                         \
        const int row = wn * 32 + np * 16 + rsel;                              \
        const uint32_t bd = sB + (uint32_t)(row << 7)                          \
                          + (uint32_t)((((ks * 2 + khalf)) ^ (row & 7)) << 4); \
        asm volatile(                                                          \
          "ldmatrix.sync.aligned.m8n8.x4.shared.b16 {%0,%1,%2,%3}, [%4];"      \
          : "=r"(b[np][0]), "=r"(b[np][1]), "=r"(b[np][2]), "=r"(b[np][3])     \
          : "r"(bd));                                                          \
      }                                                                        \
      _Pragma("unroll")                                                        \
      for (int mf = 0; mf < 4; ++mf) {                                         \
        _Pragma("unroll")                                                      \
        for (int nf = 0; nf < 4; ++nf) {                                       \
          asm volatile(                                                        \
            "mma.sync.aligned.m16n8k16.row.col.f32.bf16.bf16.f32 "             \
            "{%0,%1,%2,%3}, {%4,%5,%6,%7}, {%8,%9}, {%0,%1,%2,%3};"            \
            : "+f"(ACC[mf][nf][0]), "+f"(ACC[mf][nf][1]),                      \
              "+f"(ACC[mf][nf][2]), "+f"(ACC[mf][nf][3])                       \
            : "r"(a[mf][0]), "r"(a[mf][1]), "r"(a[mf][2]), "r"(a[mf][3]),      \
              "r"(b[nf >> 1][nf & 1]), "r"(b[nf >> 1][2 + (nf & 1)]));         \
        }                                                                      \
      }                                                                        \
    }                                                                          \
  }

__global__ __launch_bounds__(128, 2)
void lstm_hmma_kernel(const float* __restrict__ cx, float* __restrict__ out) {
    extern __shared__ char smem[];
    const uint32_t sb = smem_u32(smem);
    const int tid = threadIdx.x, lane = tid & 31, wid = tid >> 5;
    const int wm = wid >> 1, wn = wid & 1;
    const int m0 = blockIdx.y << 7, n0 = blockIdx.x << 6;
    const int rsel = lane & 15, khalf = lane >> 4;

    float acc1[4][4][4], acc2[4][4][4];
#pragma unroll
    for (int i = 0; i < 4; ++i)
#pragma unroll
        for (int j = 0; j < 4; ++j)
#pragma unroll
            for (int k = 0; k < 4; ++k) { acc1[i][j][k] = 0.0f; acc2[i][j][k] = 0.0f; }

    prefetch_chunk(sb, 0, 0, m0, n0, tid);
    asm volatile("cp.async.commit_group;");
    prefetch_chunk(sb, 1, 1, m0, n0, tid);
    asm volatile("cp.async.commit_group;");
    prefetch_chunk(sb, 2, 2, m0, n0, tid);
    asm volatile("cp.async.commit_group;");

    for (int i = 0; i < NCH; ++i) {
        asm volatile("cp.async.wait_group 2;");
        __syncthreads();
        if (i + 3 < NCH) prefetch_chunk(sb, (i + 3) & 3, i + 3, m0, n0, tid);
        asm volatile("cp.async.commit_group;");
        const uint32_t sa = sb + (uint32_t)((i & 3) * CHUNK_BYTES);
        if (i < 64) COMPUTE_CHUNK(acc1, sa) else COMPUTE_CHUNK(acc2, sa)
    }
    asm volatile("cp.async.wait_group 0;");
    __syncthreads();

    // ---------------- fused LSTM epilogue ----------------
    float* cx_sm = reinterpret_cast<float*>(smem);        // 128 x 17
    float* h_sm = cx_sm + 128 * 17;
    float* c_sm = h_sm + 128 * 17;
    const int u0 = n0 >> 2;                                // 16 units per tile
#pragma unroll
    for (int t = 0; t < 16; ++t) {
        const int idx = t * 128 + tid;
        const int r = idx >> 4, u = idx & 15;
        cx_sm[r * 17 + u] = cx[(size_t)(m0 + r) * H_DIM + u0 + u];
    }
    __syncthreads();

    const float INV = 1.0f / 16129.0f;              // 1/127^2
    const float INV2 = 5.0f / 4129024.0f;           // 1/(127*S) = 5/(127^2*256)
    const bool oddl = (lane & 1) != 0;
#pragma unroll
    for (int mf = 0; mf < 4; ++mf) {
#pragma unroll
        for (int nf = 0; nf < 4; ++nf) {
            const int col0 = wn * 32 + nf * 8 + 2 * (lane & 3);
            const float bf0 = g_bias[n0 + col0];
            const float bf1 = g_bias[n0 + col0 + 1];
            float v0 = fmaf(acc1[mf][nf][0], INV, fmaf(acc2[mf][nf][0], INV2, bf0));
            float v1 = fmaf(acc1[mf][nf][1], INV, fmaf(acc2[mf][nf][1], INV2, bf1));
            float v2 = fmaf(acc1[mf][nf][2], INV, fmaf(acc2[mf][nf][2], INV2, bf0));
            float v3 = fmaf(acc1[mf][nf][3], INV, fmaf(acc2[mf][nf][3], INV2, bf1));
            float p0 = __shfl_xor_sync(0xFFFFFFFFu, v0, 1);
            float p1 = __shfl_xor_sync(0xFFFFFFFFu, v1, 1);
            float p2 = __shfl_xor_sync(0xFFFFFFFFu, v2, 1);
            float p3 = __shfl_xor_sync(0xFFFFFFFFu, v3, 1);
            const float gf = oddl ? p2 : v0;
            const float gi = oddl ? p3 : v1;
            const float gg = oddl ? v2 : p0;
            const float go = oddl ? v3 : p1;
            const int r = wm * 64 + mf * 16 + (lane >> 2) + (oddl ? 8 : 0);
            const int ul = wn * 8 + nf * 2 + ((lane & 3) >> 1);
            const float f = fq8(sigm_(gf));
            const float ii = fq8(sigm_(gi));
            const float gq = fq8(tanh_(gg));
            const float o = fq8(sigm_(go));
            const float cn = f * cx_sm[r * 17 + ul] + ii * gq;
            h_sm[r * 17 + ul] = o * fq8(tanh_(cn));
            c_sm[r * 17 + ul] = fq8(cn);
        }
    }
    __syncthreads();

    float* hout = out;
    float* cout_ = out + (size_t)B_DIM * H_DIM;
#pragma unroll
    for (int t = 0; t < 16; ++t) {
        const int idx = t * 128 + tid;
        const int r = idx >> 4, u = idx & 15;
        hout[(size_t)(m0 + r) * H_DIM + u0 + u] = h_sm[r * 17 + u];
        cout_[(size_t)(m0 + r) * H_DIM + u0 + u] = c_sm[r * 17 + u];
    }
}

// ------------------------------- launcher ---------------------------------

extern "C" void kernel_launch(void* const* d_in, const int* in_sizes, int n_in,
                              void* d_out, int out_size) {
    (void)in_sizes; (void)n_in; (void)out_size;
    const float* x  = (const float*)d_in[0];
    const float* hx = (const float*)d_in[1];
    const float* cx = (const float*)d_in[2];
    const float* wx = (const float*)d_in[3];
    const float* bx = (const float*)d_in[4];
    const float* wh = (const float*)d_in[5];
    const float* bh = (const float*)d_in[6];
    float* out = (float*)d_out;

    cudaFuncSetAttribute(lstm_hmma_kernel,
                         cudaFuncAttributeMaxDynamicSharedMemorySize, SMEM_BYTES);

    prep_A<<<dim3(2, B_DIM), 256>>>(x, hx);
    prep_W<<<dim3(6, NTOT), 256>>>(wx, wh);
    prep_bias<<<NTOT / 256, 256>>>(bx, bh);

    dim3 grid(NTOT / 64, B_DIM / 128);          // 128 x 8 = 1024 CTAs
    lstm_hmma_kernel<<<grid, 128, SMEM_BYTES>>>(cx, out);
}

// round 13
// speedup vs baseline: 2.6371x; 1.0351x over previous
#include <cuda_runtime.h>
#include <cuda_bf16.h>
#include <cstdint>

#define B_DIM  1024
#define H_DIM  2048
#define KTOT   6144
#define NTOT   8192
#define NCH    96      // K-chunks of 64 bf16: 0-63 (x|hi) -> acc1 ; 64-95 lo -> acc2
#define NPAIR  48
#define STAGES 4
#define CHUNK_BYTES 24576            // A 128x64x2 = 16KB + B 64x64x2 = 8KB
#define SMEM_BYTES (STAGES * CHUNK_BYTES)   // 96KB

// h scale: S = 256*127/5; v = round(hx*S) in [-32511,32511]; v = hi*256 + lo
#define SCALE_H 6502.4f
#define VCLAMP  32511.0f

__device__ __align__(256) __nv_bfloat16 g_A[(size_t)B_DIM * KTOT];
__device__ __align__(256) __nv_bfloat16 g_B[(size_t)NTOT * KTOT];
__device__ float g_bias[NTOT];

// ------------------------------- helpers ----------------------------------

__device__ __forceinline__ uint32_t smem_u32(const void* p) {
    uint32_t a;
    asm("{ .reg .u64 t; cvta.to.shared.u64 t, %1; cvt.u32.u64 %0, t; }"
        : "=r"(a) : "l"(p));
    return a;
}

__device__ __forceinline__ float fq8(float v) {
    float q = rintf(v * 127.0f);
    q = fminf(127.0f, fmaxf(-127.0f, q));
    return q * (1.0f / 127.0f);
}

__device__ __forceinline__ float sigm_(float x) {
    return 1.0f / (1.0f + expf(-x));
}

__device__ __forceinline__ float tanh_(float x) {
    float e = expf(-2.0f * fabsf(x));
    return copysignf((1.0f - e) / (1.0f + e), x);
}

__device__ __forceinline__ float q127f(float w) {
    float q = rintf(w * 127.0f);
    return fminf(127.0f, fmaxf(-127.0f, q));
}

// ------------------------------ prep kernels ------------------------------

__global__ void prep_A(const float* __restrict__ x, const float* __restrict__ hx) {
    const int b = blockIdx.y;
    const int c4 = blockIdx.x * 256 + threadIdx.x;      // 0..511
    const int k = c4 << 2;
    const float4 xv = *reinterpret_cast<const float4*>(x + (size_t)b * 2048 + k);
    const float4 hv = *reinterpret_cast<const float4*>(hx + (size_t)b * 2048 + k);
    const float* xf = reinterpret_cast<const float*>(&xv);
    const float* hf = reinterpret_cast<const float*>(&hv);
    ushort4 xq, hiq, loq;
    unsigned short* xp = reinterpret_cast<unsigned short*>(&xq);
    unsigned short* hp = reinterpret_cast<unsigned short*>(&hiq);
    unsigned short* lp = reinterpret_cast<unsigned short*>(&loq);
#pragma unroll
    for (int j = 0; j < 4; ++j) {
        xp[j] = __bfloat16_as_ushort(__float2bfloat16_rn(q127f(xf[j])));
        float vf = rintf(hf[j] * SCALE_H);
        vf = fminf(VCLAMP, fmaxf(-VCLAMP, vf));
        int v = (int)vf;
        int hi = (v + 128) >> 8;            // hi in [-127,127]
        int lo = v - (hi << 8);             // lo in [-128,127]
        hp[j] = __bfloat16_as_ushort(__float2bfloat16_rn((float)hi));
        lp[j] = __bfloat16_as_ushort(__float2bfloat16_rn((float)lo));
    }
    size_t base = (size_t)b * KTOT + k;
    *reinterpret_cast<ushort4*>(g_A + base)        = xq;
    *reinterpret_cast<ushort4*>(g_A + base + 2048) = hiq;
    *reinterpret_cast<ushort4*>(g_A + base + 4096) = loq;
}

// B row r=4u+g from orig row g*2048+u: [0,2048) wxI ; [2048,4096) whI*5 ; [4096,6144) whI
__global__ void prep_W(const float* __restrict__ wx, const float* __restrict__ wh) {
    const int r = blockIdx.y;
    const int c4 = blockIdx.x * 256 + threadIdx.x;      // 0..1535
    const int u = r >> 2, g = r & 3;
    const size_t orig = (size_t)(g * H_DIM + u) * 2048;
    ushort4 outv;
    unsigned short* op = reinterpret_cast<unsigned short*>(&outv);
    if (c4 < 512) {
        const float4 wv = *reinterpret_cast<const float4*>(wx + orig + (c4 << 2));
        const float* wf = reinterpret_cast<const float*>(&wv);
#pragma unroll
        for (int j = 0; j < 4; ++j)
            op[j] = __bfloat16_as_ushort(__float2bfloat16_rn(q127f(wf[j])));
    } else if (c4 < 1024) {
        const float4 wv = *reinterpret_cast<const float4*>(wh + orig + ((c4 - 512) << 2));
        const float* wf = reinterpret_cast<const float*>(&wv);
#pragma unroll
        for (int j = 0; j < 4; ++j)
            op[j] = __bfloat16_as_ushort(__float2bfloat16_rn(5.0f * q127f(wf[j])));
    } else {
        const float4 wv = *reinterpret_cast<const float4*>(wh + orig + ((c4 - 1024) << 2));
        const float* wf = reinterpret_cast<const float*>(&wv);
#pragma unroll
        for (int j = 0; j < 4; ++j)
            op[j] = __bfloat16_as_ushort(__float2bfloat16_rn(q127f(wf[j])));
    }
    *reinterpret_cast<ushort4*>(g_B + (size_t)r * KTOT + (c4 << 2)) = outv;
}

__global__ void prep_bias(const float* __restrict__ bx, const float* __restrict__ bh) {
    int r = blockIdx.x * 256 + threadIdx.x;
    if (r >= NTOT) return;
    int u = r >> 2, g = r & 3;
    int orig = g * H_DIM + u;
    g_bias[r] = bx[orig] + bh[orig];
}

// ------------------------------- GEMM kernel ------------------------------
// CTA: 128(M) x 64(N), 128 threads, 4 warps (wm,wn in {0,1}), 2 CTAs/SM.
// Warp tile: 64(M) x 32(N). bf16 m16n8k16 HMMA, fp32 accumulators.
// Chunks processed in PAIRS: one wait_group + one barrier per 2 chunks.

__device__ __forceinline__ void prefetch_chunk(uint32_t sb, int stage, int chunk,
                                               int m0, int n0, int tid) {
    const int koff = chunk << 6;        // 64 bf16 per chunk
    const uint32_t sbase = sb + (uint32_t)stage * CHUNK_BYTES;
#pragma unroll
    for (int p = 0; p < 12; ++p) {
        const int idx = p * 128 + tid;      // 0..1535 ; <1024 A, else B
        const bool isA = idx < 1024;
        const int v = isA ? idx : idx - 1024;
        const int row = v >> 3;
        const int q = v & 7;
        const uint32_t dst = sbase + (isA ? 0u : 16384u)
                           + (uint32_t)(row << 7)
                           + (uint32_t)((q ^ (row & 7)) << 4);
        const __nv_bfloat16* src = isA
            ? g_A + (size_t)(m0 + row) * KTOT + koff + (q << 3)
            : g_B + (size_t)(n0 + row) * KTOT + koff + (q << 3);
        asm volatile("cp.async.cg.shared.global [%0], [%1], 16;"
                     :: "r"(dst), "l"(src));
    }
}

#define COMPUTE_CHUNK(ACC, SA)                                                 \
  {                                                                            \
    const uint32_t sA = (SA);                                                  \
    const uint32_t sB = sA + 16384u;                                           \
    _Pragma("unroll")                                                          \
    for (int ks = 0; ks < 4; ++ks) {                                           \
      uint32_t a[4][4], b[2][4];                                               \
      _Pragma("unroll")                                                        \
      for (int mf = 0; mf < 4; ++mf) {                                         \
        const int row = wm * 64 + mf * 16 + rsel;                              \
        const uint32_t ad = sA + (uint32_t)(row << 7)                          \
                          + (uint32_t)((((ks * 2 + khalf)) ^ (row & 7)) << 4); \
        asm volatile(                                                          \
          "ldmatrix.sync.aligned.m8n8.x4.shared.b16 {%0,%1,%2,%3}, [%4];"      \
          : "=r"(a[mf][0]), "=r"(a[mf][1]), "=r"(a[mf][2]), "=r"(a[mf][3])     \
          : "r"(ad));                                                          \
      }                                                                        \
      _Pragma("unroll")                                                        \
      for (int np = 0; np < 2; ++np) {                                         \
        const int row = wn * 32 + np * 16 + rsel;                              \
        const uint32_t bd = sB + (uint32_t)(row << 7)                          \
                          + (uint32_t)((((ks * 2 + khalf)) ^ (row & 7)) << 4); \
        asm volatile(                                                          \
          "ldmatrix.sync.aligned.m8n8.x4.shared.b16 {%0,%1,%2,%3}, [%4];"      \
          : "=r"(b[np][0]), "=r"(b[np][1]), "=r"(b[np][2]), "=r"(b[np][3])     \
          : "r"(bd));                                                          \
      }                                                                        \
      _Pragma("unroll")                                                        \
      for (int mf = 0; mf < 4; ++mf) {                                         \
        _Pragma("unroll")                                                      \
        for (int nf = 0; nf < 4; ++nf) {                                       \
          asm volatile(                                                        \
            "mma.sync.aligned.m16n8k16.row.col.f32.bf16.bf16.f32 "             \
            "{%0,%1,%2,%3}, {%4,%5,%6,%7}, {%8,%9}, {%0,%1,%2,%3};"            \
            : "+f"(ACC[mf][nf][0]), "+f"(ACC[mf][nf][1]),                      \
              "+f"(ACC[mf][nf][2]), "+f"(ACC[mf][nf][3])                       \
            : "r"(a[mf][0]), "r"(a[mf][1]), "r"(a[mf][2]), "r"(a[mf][3]),      \
              "r"(b[nf >> 1][nf & 1]), "r"(b[nf >> 1][2 + (nf & 1)]));         \
        }                                                                      \
      }                                                                        \
    }                                                                          \
  }

__global__ __launch_bounds__(128, 2)
void lstm_hmma_kernel(const float* __restrict__ cx, float* __restrict__ out) {
    extern __shared__ char smem[];
    const uint32_t sb = smem_u32(smem);
    const int tid = threadIdx.x, lane = tid & 31, wid = tid >> 5;
    const int wm = wid >> 1, wn = wid & 1;
    const int m0 = blockIdx.y << 7, n0 = blockIdx.x << 6;
    const int rsel = lane & 15, khalf = lane >> 4;

    float acc1[4][4][4], acc2[4][4][4];
#pragma unroll
    for (int i = 0; i < 4; ++i)
#pragma unroll
        for (int j = 0; j < 4; ++j)
#pragma unroll
            for (int k = 0; k < 4; ++k) { acc1[i][j][k] = 0.0f; acc2[i][j][k] = 0.0f; }

    // preload pair 0 (chunks 0,1 -> stages 0,1), one commit group per pair
    prefetch_chunk(sb, 0, 0, m0, n0, tid);
    prefetch_chunk(sb, 1, 1, m0, n0, tid);
    asm volatile("cp.async.commit_group;");

#pragma unroll 2
    for (int j = 0; j < NPAIR; ++j) {
        // pair j complete (only group possibly outstanding besides j+1 below)
        asm volatile("cp.async.wait_group 0;");
        __syncthreads();   // pair j visible to all; pair j-1 stages reusable
        if (j + 1 < NPAIR) {
            prefetch_chunk(sb, (2 * j + 2) & 3, 2 * j + 2, m0, n0, tid);
            prefetch_chunk(sb, (2 * j + 3) & 3, 2 * j + 3, m0, n0, tid);
            asm volatile("cp.async.commit_group;");
        }
        const uint32_t sa0 = sb + (uint32_t)(((2 * j) & 3) * CHUNK_BYTES);
        const uint32_t sa1 = sb + (uint32_t)(((2 * j + 1) & 3) * CHUNK_BYTES);
        if (j < 32) {
            COMPUTE_CHUNK(acc1, sa0)
            COMPUTE_CHUNK(acc1, sa1)
        } else {
            COMPUTE_CHUNK(acc2, sa0)
            COMPUTE_CHUNK(acc2, sa1)
        }
    }
    __syncthreads();

    // ---------------- fused LSTM epilogue ----------------
    float* cx_sm = reinterpret_cast<float*>(smem);        // 128 x 17
    float* h_sm = cx_sm + 128 * 17;
    float* c_sm = h_sm + 128 * 17;
    const int u0 = n0 >> 2;                                // 16 units per tile
#pragma unroll
    for (int t = 0; t < 16; ++t) {
        const int idx = t * 128 + tid;
        const int r = idx >> 4, u = idx & 15;
        cx_sm[r * 17 + u] = cx[(size_t)(m0 + r) * H_DIM + u0 + u];
    }
    __syncthreads();

    const float INV = 1.0f / 16129.0f;              // 1/127^2
    const float INV2 = 5.0f / 4129024.0f;           // 1/(127*S) = 5/(127^2*256)
    const bool oddl = (lane & 1) != 0;
#pragma unroll
    for (int mf = 0; mf < 4; ++mf) {
#pragma unroll
        for (int nf = 0; nf < 4; ++nf) {
            const int col0 = wn * 32 + nf * 8 + 2 * (lane & 3);
            const float bf0 = g_bias[n0 + col0];
            const float bf1 = g_bias[n0 + col0 + 1];
            float v0 = fmaf(acc1[mf][nf][0], INV, fmaf(acc2[mf][nf][0], INV2, bf0));
            float v1 = fmaf(acc1[mf][nf][1], INV, fmaf(acc2[mf][nf][1], INV2, bf1));
            float v2 = fmaf(acc1[mf][nf][2], INV, fmaf(acc2[mf][nf][2], INV2, bf0));
            float v3 = fmaf(acc1[mf][nf][3], INV, fmaf(acc2[mf][nf][3], INV2, bf1));
            float p0 = __shfl_xor_sync(0xFFFFFFFFu, v0, 1);
            float p1 = __shfl_xor_sync(0xFFFFFFFFu, v1, 1);
            float p2 = __shfl_xor_sync(0xFFFFFFFFu, v2, 1);
            float p3 = __shfl_xor_sync(0xFFFFFFFFu, v3, 1);
            const float gf = oddl ? p2 : v0;
            const float gi = oddl ? p3 : v1;
            const float gg = oddl ? v2 : p0;
            const float go = oddl ? v3 : p1;
            const int r = wm * 64 + mf * 16 + (lane >> 2) + (oddl ? 8 : 0);
            const int ul = wn * 8 + nf * 2 + ((lane & 3) >> 1);
            const float f = fq8(sigm_(gf));
            const float ii = fq8(sigm_(gi));
            const float gq = fq8(tanh_(gg));
            const float o = fq8(sigm_(go));
            const float cn = f * cx_sm[r * 17 + ul] + ii * gq;
            h_sm[r * 17 + ul] = o * fq8(tanh_(cn));
            c_sm[r * 17 + ul] = fq8(cn);
        }
    }
    __syncthreads();

    float* hout = out;
    float* cout_ = out + (size_t)B_DIM * H_DIM;
#pragma unroll
    for (int t = 0; t < 16; ++t) {
        const int idx = t * 128 + tid;
        const int r = idx >> 4, u = idx & 15;
        hout[(size_t)(m0 + r) * H_DIM + u0 + u] = h_sm[r * 17 + u];
        cout_[(size_t)(m0 + r) * H_DIM + u0 + u] = c_sm[r * 17 + u];
    }
}

// ------------------------------- launcher ---------------------------------

extern "C" void kernel_launch(void* const* d_in, const int* in_sizes, int n_in,
                              void* d_out, int out_size) {
    (void)in_sizes; (void)n_in; (void)out_size;
    const float* x  = (const float*)d_in[0];
    const float* hx = (const float*)d_in[1];
    const float* cx = (const float*)d_in[2];
    const float* wx = (const float*)d_in[3];
    const float* bx = (const float*)d_in[4];
    const float* wh = (const float*)d_in[5];
    const float* bh = (const float*)d_in[6];
    float* out = (float*)d_out;

    cudaFuncSetAttribute(lstm_hmma_kernel,
                         cudaFuncAttributeMaxDynamicSharedMemorySize, SMEM_BYTES);

    prep_A<<<dim3(2, B_DIM), 256>>>(x, hx);
    prep_W<<<dim3(6, NTOT), 256>>>(wx, wh);
    prep_bias<<<NTOT / 256, 256>>>(bx, bh);

    dim3 grid(NTOT / 64, B_DIM / 128);          // 128 x 8 = 1024 CTAs
    lstm_hmma_kernel<<<grid, 128, SMEM_BYTES>>>(cx, out);
}

// round 14
// speedup vs baseline: 2.6485x; 1.0043x over previous
#include <cuda_runtime.h>
#include <cuda_bf16.h>
#include <cstdint>

#define B_DIM  1024
#define H_DIM  2048
#define KTOT   6144
#define NTOT   8192
#define NCH    96      // K-chunks of 64 bf16: 0-63 (x|hi) -> acc1 ; 64-95 lo -> acc2
#define NPAIR  48
#define STAGES 4
#define CHUNK_BYTES 24576            // A 128x64x2 = 16KB + B 64x64x2 = 8KB
#define SMEM_BYTES (STAGES * CHUNK_BYTES)   // 96KB

// h scale: S = 256*127/5; v = round(hx*S) in [-32511,32511]; v = hi*256 + lo
#define SCALE_H 6502.4f
#define VCLAMP  32511.0f

__device__ __align__(256) __nv_bfloat16 g_A[(size_t)B_DIM * KTOT];
__device__ __align__(256) __nv_bfloat16 g_B[(size_t)NTOT * KTOT];
__device__ float g_bias[NTOT];

// ------------------------------- helpers ----------------------------------

__device__ __forceinline__ uint32_t smem_u32(const void* p) {
    uint32_t a;
    asm("{ .reg .u64 t; cvta.to.shared.u64 t, %1; cvt.u32.u64 %0, t; }"
        : "=r"(a) : "l"(p));
    return a;
}

__device__ __forceinline__ float fq8(float v) {
    float q = rintf(v * 127.0f);
    q = fminf(127.0f, fmaxf(-127.0f, q));
    return q * (1.0f / 127.0f);
}

__device__ __forceinline__ float sigm_(float x) {
    return 1.0f / (1.0f + expf(-x));
}

__device__ __forceinline__ float tanh_(float x) {
    float e = expf(-2.0f * fabsf(x));
    return copysignf((1.0f - e) / (1.0f + e), x);
}

__device__ __forceinline__ float q127f(float w) {
    float q = rintf(w * 127.0f);
    return fminf(127.0f, fmaxf(-127.0f, q));
}

// ------------------------------ prep kernels ------------------------------

__global__ void prep_A(const float* __restrict__ x, const float* __restrict__ hx) {
    const int b = blockIdx.y;
    const int c4 = blockIdx.x * 256 + threadIdx.x;      // 0..511
    const int k = c4 << 2;
    const float4 xv = *reinterpret_cast<const float4*>(x + (size_t)b * 2048 + k);
    const float4 hv = *reinterpret_cast<const float4*>(hx + (size_t)b * 2048 + k);
    const float* xf = reinterpret_cast<const float*>(&xv);
    const float* hf = reinterpret_cast<const float*>(&hv);
    ushort4 xq, hiq, loq;
    unsigned short* xp = reinterpret_cast<unsigned short*>(&xq);
    unsigned short* hp = reinterpret_cast<unsigned short*>(&hiq);
    unsigned short* lp = reinterpret_cast<unsigned short*>(&loq);
#pragma unroll
    for (int j = 0; j < 4; ++j) {
        xp[j] = __bfloat16_as_ushort(__float2bfloat16_rn(q127f(xf[j])));
        float vf = rintf(hf[j] * SCALE_H);
        vf = fminf(VCLAMP, fmaxf(-VCLAMP, vf));
        int v = (int)vf;
        int hi = (v + 128) >> 8;            // hi in [-127,127]
        int lo = v - (hi << 8);             // lo in [-128,127]
        hp[j] = __bfloat16_as_ushort(__float2bfloat16_rn((float)hi));
        lp[j] = __bfloat16_as_ushort(__float2bfloat16_rn((float)lo));
    }
    size_t base = (size_t)b * KTOT + k;
    *reinterpret_cast<ushort4*>(g_A + base)        = xq;
    *reinterpret_cast<ushort4*>(g_A + base + 2048) = hiq;
    *reinterpret_cast<ushort4*>(g_A + base + 4096) = loq;
}

// B row r=4u+g from orig row g*2048+u: [0,2048) wxI ; [2048,4096) whI*5 ; [4096,6144) whI
__global__ void prep_W(const float* __restrict__ wx, const float* __restrict__ wh) {
    const int r = blockIdx.y;
    const int c4 = blockIdx.x * 256 + threadIdx.x;      // 0..1535
    const int u = r >> 2, g = r & 3;
    const size_t orig = (size_t)(g * H_DIM + u) * 2048;
    ushort4 outv;
    unsigned short* op = reinterpret_cast<unsigned short*>(&outv);
    if (c4 < 512) {
        const float4 wv = *reinterpret_cast<const float4*>(wx + orig + (c4 << 2));
        const float* wf = reinterpret_cast<const float*>(&wv);
#pragma unroll
        for (int j = 0; j < 4; ++j)
            op[j] = __bfloat16_as_ushort(__float2bfloat16_rn(q127f(wf[j])));
    } else if (c4 < 1024) {
        const float4 wv = *reinterpret_cast<const float4*>(wh + orig + ((c4 - 512) << 2));
        const float* wf = reinterpret_cast<const float*>(&wv);
#pragma unroll
        for (int j = 0; j < 4; ++j)
            op[j] = __bfloat16_as_ushort(__float2bfloat16_rn(5.0f * q127f(wf[j])));
    } else {
        const float4 wv = *reinterpret_cast<const float4*>(wh + orig + ((c4 - 1024) << 2));
        const float* wf = reinterpret_cast<const float*>(&wv);
#pragma unroll
        for (int j = 0; j < 4; ++j)
            op[j] = __bfloat16_as_ushort(__float2bfloat16_rn(q127f(wf[j])));
    }
    *reinterpret_cast<ushort4*>(g_B + (size_t)r * KTOT + (c4 << 2)) = outv;
}

__global__ void prep_bias(const float* __restrict__ bx, const float* __restrict__ bh) {
    int r = blockIdx.x * 256 + threadIdx.x;
    if (r >= NTOT) return;
    int u = r >> 2, g = r & 3;
    int orig = g * H_DIM + u;
    g_bias[r] = bx[orig] + bh[orig];
}

// ------------------------------- GEMM kernel ------------------------------
// CTA: 128(M) x 64(N), 128 threads, 4 warps (wm,wn in {0,1}), 2 CTAs/SM.
// Warp tile: 64(M) x 32(N). bf16 m16n8k16 HMMA, fp32 accumulators.
// ldmatrix/mma are NON-volatile (CUTLASS style) so ptxas can software-
// pipeline LDSM of ks+1 under HMMA of ks; ldmatrix keeps a "memory"
// clobber so it cannot move across the volatile barriers / cp.async ops.

__device__ __forceinline__ void prefetch_chunk(uint32_t sb, int stage, int chunk,
                                               int m0, int n0, int tid) {
    const int koff = chunk << 6;        // 64 bf16 per chunk
    const uint32_t sbase = sb + (uint32_t)stage * CHUNK_BYTES;
#pragma unroll
    for (int p = 0; p < 12; ++p) {
        const int idx = p * 128 + tid;      // 0..1535 ; <1024 A, else B
        const bool isA = idx < 1024;
        const int v = isA ? idx : idx - 1024;
        const int row = v >> 3;
        const int q = v & 7;
        const uint32_t dst = sbase + (isA ? 0u : 16384u)
                           + (uint32_t)(row << 7)
                           + (uint32_t)((q ^ (row & 7)) << 4);
        const __nv_bfloat16* src = isA
            ? g_A + (size_t)(m0 + row) * KTOT + koff + (q << 3)
            : g_B + (size_t)(n0 + row) * KTOT + koff + (q << 3);
        asm volatile("cp.async.cg.shared.global [%0], [%1], 16;"
                     :: "r"(dst), "l"(src));
    }
}

#define COMPUTE_CHUNK(ACC, SA)                                                 \
  {                                                                            \
    const uint32_t sA = (SA);                                                  \
    const uint32_t sB = sA + 16384u;                                           \
    _Pragma("unroll")                                                          \
    for (int ks = 0; ks < 4; ++ks) {                                           \
      uint32_t a[4][4], b[2][4];                                               \
      _Pragma("unroll")                                                        \
      for (int mf = 0; mf < 4; ++mf) {                                         \
        const int row = wm * 64 + mf * 16 + rsel;                              \
        const uint32_t ad = sA + (uint32_t)(row << 7)                          \
                          + (uint32_t)((((ks * 2 + khalf)) ^ (row & 7)) << 4); \
        asm("ldmatrix.sync.aligned.m8n8.x4.shared.b16 {%0,%1,%2,%3}, [%4];"    \
          : "=r"(a[mf][0]), "=r"(a[mf][1]), "=r"(a[mf][2]), "=r"(a[mf][3])     \
          : "r"(ad) : "memory");                                               \
      }                                                                        \
      _Pragma("unroll")                                                        \
      for (int np = 0; np < 2; ++np) {                                         \
        const int row = wn * 32 + np * 16 + rsel;                              \
        const uint32_t bd = sB + (uint32_t)(row << 7)                          \
                          + (uint32_t)((((ks * 2 + khalf)) ^ (row & 7)) << 4); \
        asm("ldmatrix.sync.aligned.m8n8.x4.shared.b16 {%0,%1,%2,%3}, [%4];"    \
          : "=r"(b[np][0]), "=r"(b[np][1]), "=r"(b[np][2]), "=r"(b[np][3])     \
          : "r"(bd) : "memory");                                               \
      }                                                                        \
      _Pragma("unroll")                                                        \
      for (int mf = 0; mf < 4; ++mf) {                                         \
        _Pragma("unroll")                                                      \
        for (int nf = 0; nf < 4; ++nf) {                                       \
          asm("mma.sync.aligned.m16n8k16.row.col.f32.bf16.bf16.f32 "           \
            "{%0,%1,%2,%3}, {%4,%5,%6,%7}, {%8,%9}, {%0,%1,%2,%3};"            \
            : "+f"(ACC[mf][nf][0]), "+f"(ACC[mf][nf][1]),                      \
              "+f"(ACC[mf][nf][2]), "+f"(ACC[mf][nf][3])                       \
            : "r"(a[mf][0]), "r"(a[mf][1]), "r"(a[mf][2]), "r"(a[mf][3]),      \
              "r"(b[nf >> 1][nf & 1]), "r"(b[nf >> 1][2 + (nf & 1)]));         \
        }                                                                      \
      }                                                                        \
    }                                                                          \
  }

__global__ __launch_bounds__(128, 2)
void lstm_hmma_kernel(const float* __restrict__ cx, float* __restrict__ out) {
    extern __shared__ char smem[];
    const uint32_t sb = smem_u32(smem);
    const int tid = threadIdx.x, lane = tid & 31, wid = tid >> 5;
    const int wm = wid >> 1, wn = wid & 1;
    const int m0 = blockIdx.y << 7, n0 = blockIdx.x << 6;
    const int rsel = lane & 15, khalf = lane >> 4;

    float acc1[4][4][4], acc2[4][4][4];
#pragma unroll
    for (int i = 0; i < 4; ++i)
#pragma unroll
        for (int j = 0; j < 4; ++j)
#pragma unroll
            for (int k = 0; k < 4; ++k) { acc1[i][j][k] = 0.0f; acc2[i][j][k] = 0.0f; }

    // preload pair 0 (chunks 0,1 -> stages 0,1), one commit group per pair
    prefetch_chunk(sb, 0, 0, m0, n0, tid);
    prefetch_chunk(sb, 1, 1, m0, n0, tid);
    asm volatile("cp.async.commit_group;");

#pragma unroll 2
    for (int j = 0; j < NPAIR; ++j) {
        asm volatile("cp.async.wait_group 0;");
        __syncthreads();   // pair j visible; pair j-1 stages reusable
        if (j + 1 < NPAIR) {
            prefetch_chunk(sb, (2 * j + 2) & 3, 2 * j + 2, m0, n0, tid);
            prefetch_chunk(sb, (2 * j + 3) & 3, 2 * j + 3, m0, n0, tid);
            asm volatile("cp.async.commit_group;");
        }
        const uint32_t sa0 = sb + (uint32_t)(((2 * j) & 3) * CHUNK_BYTES);
        const uint32_t sa1 = sb + (uint32_t)(((2 * j + 1) & 3) * CHUNK_BYTES);
        if (j < 32) {
            COMPUTE_CHUNK(acc1, sa0)
            COMPUTE_CHUNK(acc1, sa1)
        } else {
            COMPUTE_CHUNK(acc2, sa0)
            COMPUTE_CHUNK(acc2, sa1)
        }
    }
    __syncthreads();

    // ---------------- fused LSTM epilogue ----------------
    float* cx_sm = reinterpret_cast<float*>(smem);        // 128 x 17
    float* h_sm = cx_sm + 128 * 17;
    float* c_sm = h_sm + 128 * 17;
    const int u0 = n0 >> 2;                                // 16 units per tile
#pragma unroll
    for (int t = 0; t < 16; ++t) {
        const int idx = t * 128 + tid;
        const int r = idx >> 4, u = idx & 15;
        cx_sm[r * 17 + u] = cx[(size_t)(m0 + r) * H_DIM + u0 + u];
    }
    __syncthreads();

    const float INV = 1.0f / 16129.0f;              // 1/127^2
    const float INV2 = 5.0f / 4129024.0f;           // 1/(127*S) = 5/(127^2*256)
    const bool oddl = (lane & 1) != 0;
#pragma unroll
    for (int mf = 0; mf < 4; ++mf) {
#pragma unroll
        for (int nf = 0; nf < 4; ++nf) {
            const int col0 = wn * 32 + nf * 8 + 2 * (lane & 3);
            const float bf0 = g_bias[n0 + col0];
            const float bf1 = g_bias[n0 + col0 + 1];
            float v0 = fmaf(acc1[mf][nf][0], INV, fmaf(acc2[mf][nf][0], INV2, bf0));
            float v1 = fmaf(acc1[mf][nf][1], INV, fmaf(acc2[mf][nf][1], INV2, bf1));
            float v2 = fmaf(acc1[mf][nf][2], INV, fmaf(acc2[mf][nf][2], INV2, bf0));
            float v3 = fmaf(acc1[mf][nf][3], INV, fmaf(acc2[mf][nf][3], INV2, bf1));
            float p0 = __shfl_xor_sync(0xFFFFFFFFu, v0, 1);
            float p1 = __shfl_xor_sync(0xFFFFFFFFu, v1, 1);
            float p2 = __shfl_xor_sync(0xFFFFFFFFu, v2, 1);
            float p3 = __shfl_xor_sync(0xFFFFFFFFu, v3, 1);
            const float gf = oddl ? p2 : v0;
            const float gi = oddl ? p3 : v1;
            const float gg = oddl ? v2 : p0;
            const float go = oddl ? v3 : p1;
            const int r = wm * 64 + mf * 16 + (lane >> 2) + (oddl ? 8 : 0);
            const int ul = wn * 8 + nf * 2 + ((lane & 3) >> 1);
            const float f = fq8(sigm_(gf));
            const float ii = fq8(sigm_(gi));
            const float gq = fq8(tanh_(gg));
            const float o = fq8(sigm_(go));
            const float cn = f * cx_sm[r * 17 + ul] + ii * gq;
            h_sm[r * 17 + ul] = o * fq8(tanh_(cn));
            c_sm[r * 17 + ul] = fq8(cn);
        }
    }
    __syncthreads();

    float* hout = out;
    float* cout_ = out + (size_t)B_DIM * H_DIM;
#pragma unroll
    for (int t = 0; t < 16; ++t) {
        const int idx = t * 128 + tid;
        const int r = idx >> 4, u = idx & 15;
        hout[(size_t)(m0 + r) * H_DIM + u0 + u] = h_sm[r * 17 + u];
        cout_[(size_t)(m0 + r) * H_DIM + u0 + u] = c_sm[r * 17 + u];
    }
}

// ------------------------------- launcher ---------------------------------

extern "C" void kernel_launch(void* const* d_in, const int* in_sizes, int n_in,
                              void* d_out, int out_size) {
    (void)in_sizes; (void)n_in; (void)out_size;
    const float* x  = (const float*)d_in[0];
    const float* hx = (const float*)d_in[1];
    const float* cx = (const float*)d_in[2];
    const float* wx = (const float*)d_in[3];
    const float* bx = (const float*)d_in[4];
    const float* wh = (const float*)d_in[5];
    const float* bh = (const float*)d_in[6];
    float* out = (float*)d_out;

    cudaFuncSetAttribute(lstm_hmma_kernel,
                         cudaFuncAttributeMaxDynamicSharedMemorySize, SMEM_BYTES);

    prep_A<<<dim3(2, B_DIM), 256>>>(x, hx);
    prep_W<<<dim3(6, NTOT), 256>>>(wx, wh);
    prep_bias<<<NTOT / 256, 256>>>(bx, bh);

    dim3 grid(NTOT / 64, B_DIM / 128);          // 128 x 8 = 1024 CTAs
    lstm_hmma_kernel<<<grid, 128, SMEM_BYTES>>>(cx, out);
}

// round 15
// speedup vs baseline: 2.8196x; 1.0646x over previous
#include <cuda_runtime.h>
#include <cuda_bf16.h>
#include <cstdint>

#define B_DIM  1024
#define H_DIM  2048
#define KTOT   6144
#define NTOT   8192
#define NCH    96      // K-chunks of 64 bf16: 0-63 (x|hi) -> acc1 ; 64-95 lo -> acc2
#define NPAIR  48
#define STAGES 4
#define CHUNK_BYTES 24576            // A 128x64x2 = 16KB + B 64x64x2 = 8KB
#define SMEM_BYTES (STAGES * CHUNK_BYTES)   // 96KB

// h scale: S = 256*127/5; v = round(hx*S) in [-32511,32511]; v = hi*256 + lo
#define SCALE_H 6502.4f
#define VCLAMP  32511.0f

__device__ __align__(256) __nv_bfloat16 g_A[(size_t)B_DIM * KTOT];
__device__ __align__(256) __nv_bfloat16 g_B[(size_t)NTOT * KTOT];
__device__ float g_bias[NTOT];

// ------------------------------- helpers ----------------------------------

__device__ __forceinline__ uint32_t smem_u32(const void* p) {
    uint32_t a;
    asm("{ .reg .u64 t; cvta.to.shared.u64 t, %1; cvt.u32.u64 %0, t; }"
        : "=r"(a) : "l"(p));
    return a;
}

__device__ __forceinline__ float fq8(float v) {
    float q = rintf(v * 127.0f);
    q = fminf(127.0f, fmaxf(-127.0f, q));
    return q * (1.0f / 127.0f);
}

__device__ __forceinline__ float sigm_(float x) {
    return 1.0f / (1.0f + expf(-x));
}

__device__ __forceinline__ float tanh_(float x) {
    float e = expf(-2.0f * fabsf(x));
    return copysignf((1.0f - e) / (1.0f + e), x);
}

__device__ __forceinline__ float q127f(float w) {
    float q = rintf(w * 127.0f);
    return fminf(127.0f, fmaxf(-127.0f, q));
}

// ------------------------------ prep kernels ------------------------------

__global__ void prep_A(const float* __restrict__ x, const float* __restrict__ hx) {
    const int b = blockIdx.y;
    const int c4 = blockIdx.x * 256 + threadIdx.x;      // 0..511
    const int k = c4 << 2;
    const float4 xv = *reinterpret_cast<const float4*>(x + (size_t)b * 2048 + k);
    const float4 hv = *reinterpret_cast<const float4*>(hx + (size_t)b * 2048 + k);
    const float* xf = reinterpret_cast<const float*>(&xv);
    const float* hf = reinterpret_cast<const float*>(&hv);
    ushort4 xq, hiq, loq;
    unsigned short* xp = reinterpret_cast<unsigned short*>(&xq);
    unsigned short* hp = reinterpret_cast<unsigned short*>(&hiq);
    unsigned short* lp = reinterpret_cast<unsigned short*>(&loq);
#pragma unroll
    for (int j = 0; j < 4; ++j) {
        xp[j] = __bfloat16_as_ushort(__float2bfloat16_rn(q127f(xf[j])));
        float vf = rintf(hf[j] * SCALE_H);
        vf = fminf(VCLAMP, fmaxf(-VCLAMP, vf));
        int v = (int)vf;
        int hi = (v + 128) >> 8;            // hi in [-127,127]
        int lo = v - (hi << 8);             // lo in [-128,127]
        hp[j] = __bfloat16_as_ushort(__float2bfloat16_rn((float)hi));
        lp[j] = __bfloat16_as_ushort(__float2bfloat16_rn((float)lo));
    }
    size_t base = (size_t)b * KTOT + k;
    *reinterpret_cast<ushort4*>(g_A + base)        = xq;
    *reinterpret_cast<ushort4*>(g_A + base + 2048) = hiq;
    *reinterpret_cast<ushort4*>(g_A + base + 4096) = loq;
}

// B row r=4u+g from orig row g*2048+u: [0,2048) wxI ; [2048,4096) whI*5 ; [4096,6144) whI
__global__ void prep_W(const float* __restrict__ wx, const float* __restrict__ wh) {
    const int r = blockIdx.y;
    const int c4 = blockIdx.x * 256 + threadIdx.x;      // 0..1535
    const int u = r >> 2, g = r & 3;
    const size_t orig = (size_t)(g * H_DIM + u) * 2048;
    ushort4 outv;
    unsigned short* op = reinterpret_cast<unsigned short*>(&outv);
    if (c4 < 512) {
        const float4 wv = *reinterpret_cast<const float4*>(wx + orig + (c4 << 2));
        const float* wf = reinterpret_cast<const float*>(&wv);
#pragma unroll
        for (int j = 0; j < 4; ++j)
            op[j] = __bfloat16_as_ushort(__float2bfloat16_rn(q127f(wf[j])));
    } else if (c4 < 1024) {
        const float4 wv = *reinterpret_cast<const float4*>(wh + orig + ((c4 - 512) << 2));
        const float* wf = reinterpret_cast<const float*>(&wv);
#pragma unroll
        for (int j = 0; j < 4; ++j)
            op[j] = __bfloat16_as_ushort(__float2bfloat16_rn(5.0f * q127f(wf[j])));
    } else {
        const float4 wv = *reinterpret_cast<const float4*>(wh + orig + ((c4 - 1024) << 2));
        const float* wf = reinterpret_cast<const float*>(&wv);
#pragma unroll
        for (int j = 0; j < 4; ++j)
            op[j] = __bfloat16_as_ushort(__float2bfloat16_rn(q127f(wf[j])));
    }
    *reinterpret_cast<ushort4*>(g_B + (size_t)r * KTOT + (c4 << 2)) = outv;
}

__global__ void prep_bias(const float* __restrict__ bx, const float* __restrict__ bh) {
    int r = blockIdx.x * 256 + threadIdx.x;
    if (r >= NTOT) return;
    int u = r >> 2, g = r & 3;
    int orig = g * H_DIM + u;
    g_bias[r] = bx[orig] + bh[orig];
}

// ------------------------------- GEMM kernel ------------------------------
// CTA: 128(M) x 64(N), 256 threads, 8 warps (wm=wid>>1 in 0..3, wn=wid&1),
// warp tile 32(M) x 32(N), 2 CTAs/SM -> 16 warps/SM (4/SMSP) for latency hiding.

__device__ __forceinline__ void prefetch_chunk(uint32_t sb, int stage, int chunk,
                                               int m0, int n0, int tid) {
    const int koff = chunk << 6;        // 64 bf16 per chunk
    const uint32_t sbase = sb + (uint32_t)stage * CHUNK_BYTES;
#pragma unroll
    for (int p = 0; p < 6; ++p) {
        const int idx = p * 256 + tid;      // 0..1535 ; <1024 A, else B
        const bool isA = idx < 1024;
        const int v = isA ? idx : idx - 1024;
        const int row = v >> 3;
        const int q = v & 7;
        const uint32_t dst = sbase + (isA ? 0u : 16384u)
                           + (uint32_t)(row << 7)
                           + (uint32_t)((q ^ (row & 7)) << 4);
        const __nv_bfloat16* src = isA
            ? g_A + (size_t)(m0 + row) * KTOT + koff + (q << 3)
            : g_B + (size_t)(n0 + row) * KTOT + koff + (q << 3);
        asm volatile("cp.async.cg.shared.global [%0], [%1], 16;"
                     :: "r"(dst), "l"(src));
    }
}

#define COMPUTE_CHUNK(ACC, SA)                                                 \
  {                                                                            \
    const uint32_t sA = (SA);                                                  \
    const uint32_t sB = sA + 16384u;                                           \
    _Pragma("unroll")                                                          \
    for (int ks = 0; ks < 4; ++ks) {                                           \
      uint32_t a[2][4], b[2][4];                                               \
      _Pragma("unroll")                                                        \
      for (int mf = 0; mf < 2; ++mf) {                                         \
        const int row = wm * 32 + mf * 16 + rsel;                              \
        const uint32_t ad = sA + (uint32_t)(row << 7)                          \
                          + (uint32_t)((((ks * 2 + khalf)) ^ (row & 7)) << 4); \
        asm("ldmatrix.sync.aligned.m8n8.x4.shared.b16 {%0,%1,%2,%3}, [%4];"    \
          : "=r"(a[mf][0]), "=r"(a[mf][1]), "=r"(a[mf][2]), "=r"(a[mf][3])     \
          : "r"(ad) : "memory");                                               \
      }                                                                        \
      _Pragma("unroll")                                                        \
      for (int np = 0; np < 2; ++np) {                                         \
        const int row = wn * 32 + np * 16 + rsel;                              \
        const uint32_t bd = sB + (uint32_t)(row << 7)                          \
                          + (uint32_t)((((ks * 2 + khalf)) ^ (row & 7)) << 4); \
        asm("ldmatrix.sync.aligned.m8n8.x4.shared.b16 {%0,%1,%2,%3}, [%4];"    \
          : "=r"(b[np][0]), "=r"(b[np][1]), "=r"(b[np][2]), "=r"(b[np][3])     \
          : "r"(bd) : "memory");                                               \
      }                                                                        \
      _Pragma("unroll")                                                        \
      for (int mf = 0; mf < 2; ++mf) {                                         \
        _Pragma("unroll")                                                      \
        for (int nf = 0; nf < 4; ++nf) {                                       \
          asm("mma.sync.aligned.m16n8k16.row.col.f32.bf16.bf16.f32 "           \
            "{%0,%1,%2,%3}, {%4,%5,%6,%7}, {%8,%9}, {%0,%1,%2,%3};"            \
            : "+f"(ACC[mf][nf][0]), "+f"(ACC[mf][nf][1]),                      \
              "+f"(ACC[mf][nf][2]), "+f"(ACC[mf][nf][3])                       \
            : "r"(a[mf][0]), "r"(a[mf][1]), "r"(a[mf][2]), "r"(a[mf][3]),      \
              "r"(b[nf >> 1][nf & 1]), "r"(b[nf >> 1][2 + (nf & 1)]));         \
        }                                                                      \
      }                                                                        \
    }                                                                          \
  }

__global__ __launch_bounds__(256, 2)
void lstm_hmma_kernel(const float* __restrict__ cx, float* __restrict__ out) {
    extern __shared__ char smem[];
    const uint32_t sb = smem_u32(smem);
    const int tid = threadIdx.x, lane = tid & 31, wid = tid >> 5;
    const int wm = wid >> 1, wn = wid & 1;     // wm 0..3 (M), wn 0..1 (N)
    const int m0 = blockIdx.y << 7, n0 = blockIdx.x << 6;
    const int rsel = lane & 15, khalf = lane >> 4;

    float acc1[2][4][4], acc2[2][4][4];
#pragma unroll
    for (int i = 0; i < 2; ++i)
#pragma unroll
        for (int j = 0; j < 4; ++j)
#pragma unroll
            for (int k = 0; k < 4; ++k) { acc1[i][j][k] = 0.0f; acc2[i][j][k] = 0.0f; }

    // preload pair 0 (chunks 0,1 -> stages 0,1), one commit group per pair
    prefetch_chunk(sb, 0, 0, m0, n0, tid);
    prefetch_chunk(sb, 1, 1, m0, n0, tid);
    asm volatile("cp.async.commit_group;");

#pragma unroll 2
    for (int j = 0; j < NPAIR; ++j) {
        asm volatile("cp.async.wait_group 0;");
        __syncthreads();   // pair j visible; pair j-1 stages reusable
        if (j + 1 < NPAIR) {
            prefetch_chunk(sb, (2 * j + 2) & 3, 2 * j + 2, m0, n0, tid);
            prefetch_chunk(sb, (2 * j + 3) & 3, 2 * j + 3, m0, n0, tid);
            asm volatile("cp.async.commit_group;");
        }
        const uint32_t sa0 = sb + (uint32_t)(((2 * j) & 3) * CHUNK_BYTES);
        const uint32_t sa1 = sb + (uint32_t)(((2 * j + 1) & 3) * CHUNK_BYTES);
        if (j < 32) {
            COMPUTE_CHUNK(acc1, sa0)
            COMPUTE_CHUNK(acc1, sa1)
        } else {
            COMPUTE_CHUNK(acc2, sa0)
            COMPUTE_CHUNK(acc2, sa1)
        }
    }
    __syncthreads();

    // ---------------- fused LSTM epilogue ----------------
    float* cx_sm = reinterpret_cast<float*>(smem);        // 128 x 17
    float* h_sm = cx_sm + 128 * 17;
    float* c_sm = h_sm + 128 * 17;
    const int u0 = n0 >> 2;                                // 16 units per tile
#pragma unroll
    for (int t = 0; t < 8; ++t) {
        const int idx = t * 256 + tid;
        const int r = idx >> 4, u = idx & 15;
        cx_sm[r * 17 + u] = cx[(size_t)(m0 + r) * H_DIM + u0 + u];
    }
    __syncthreads();

    const float INV = 1.0f / 16129.0f;              // 1/127^2
    const float INV2 = 5.0f / 4129024.0f;           // 1/(127*S) = 5/(127^2*256)
    const bool oddl = (lane & 1) != 0;
#pragma unroll
    for (int mf = 0; mf < 2; ++mf) {
#pragma unroll
        for (int nf = 0; nf < 4; ++nf) {
            const int col0 = wn * 32 + nf * 8 + 2 * (lane & 3);
            const float bf0 = g_bias[n0 + col0];
            const float bf1 = g_bias[n0 + col0 + 1];
            float v0 = fmaf(acc1[mf][nf][0], INV, fmaf(acc2[mf][nf][0], INV2, bf0));
            float v1 = fmaf(acc1[mf][nf][1], INV, fmaf(acc2[mf][nf][1], INV2, bf1));
            float v2 = fmaf(acc1[mf][nf][2], INV, fmaf(acc2[mf][nf][2], INV2, bf0));
            float v3 = fmaf(acc1[mf][nf][3], INV, fmaf(acc2[mf][nf][3], INV2, bf1));
            float p0 = __shfl_xor_sync(0xFFFFFFFFu, v0, 1);
            float p1 = __shfl_xor_sync(0xFFFFFFFFu, v1, 1);
            float p2 = __shfl_xor_sync(0xFFFFFFFFu, v2, 1);
            float p3 = __shfl_xor_sync(0xFFFFFFFFu, v3, 1);
            const float gf = oddl ? p2 : v0;
            const float gi = oddl ? p3 : v1;
            const float gg = oddl ? v2 : p0;
            const float go = oddl ? v3 : p1;
            const int r = wm * 32 + mf * 16 + (lane >> 2) + (oddl ? 8 : 0);
            const int ul = wn * 8 + nf * 2 + ((lane & 3) >> 1);
            const float f = fq8(sigm_(gf));
            const float ii = fq8(sigm_(gi));
            const float gq = fq8(tanh_(gg));
            const float o = fq8(sigm_(go));
            const float cn = f * cx_sm[r * 17 + ul] + ii * gq;
            h_sm[r * 17 + ul] = o * fq8(tanh_(cn));
            c_sm[r * 17 + ul] = fq8(cn);
        }
    }
    __syncthreads();

    float* hout = out;
    float* cout_ = out + (size_t)B_DIM * H_DIM;
#pragma unroll
    for (int t = 0; t < 8; ++t) {
        const int idx = t * 256 + tid;
        const int r = idx >> 4, u = idx & 15;
        hout[(size_t)(m0 + r) * H_DIM + u0 + u] = h_sm[r * 17 + u];
        cout_[(size_t)(m0 + r) * H_DIM + u0 + u] = c_sm[r * 17 + u];
    }
}

// ------------------------------- launcher ---------------------------------

extern "C" void kernel_launch(void* const* d_in, const int* in_sizes, int n_in,
                              void* d_out, int out_size) {
    (void)in_sizes; (void)n_in; (void)out_size;
    const float* x  = (const float*)d_in[0];
    const float* hx = (const float*)d_in[1];
    const float* cx = (const float*)d_in[2];
    const float* wx = (const float*)d_in[3];
    const float* bx = (const float*)d_in[4];
    const float* wh = (const float*)d_in[5];
    const float* bh = (const float*)d_in[6];
    float* out = (float*)d_out;

    cudaFuncSetAttribute(lstm_hmma_kernel,
                         cudaFuncAttributeMaxDynamicSharedMemorySize, SMEM_BYTES);

    prep_A<<<dim3(2, B_DIM), 256>>>(x, hx);
    prep_W<<<dim3(6, NTOT), 256>>>(wx, wh);
    prep_bias<<<NTOT / 256, 256>>>(bx, bh);

    dim3 grid(NTOT / 64, B_DIM / 128);          // 128 x 8 = 1024 CTAs
    lstm_hmma_kernel<<<grid, 256, SMEM_BYTES>>>(cx, out);
}